// round 14
// baseline (speedup 1.0000x reference)
#include <cuda_runtime.h>
#include <math.h>

// ---------------------------------------------------------------------------
// DiMap SPD pipeline, round 13 (identical to round 12; prior bench was an
// infra failure — resubmitting to get a clean A/B signal).
// R11 minus the accuracy risk: JTOL1S back to 1e-5 (rel_err ~2.7e-5, 35x
// margin), compensated by exact structural savings:
//  - trsm restricted to the live lower-triangular region (X is lower-tri)
//  - triangular-A matmul (mm_ltA) for F_b = L_G W' and Fm = Li0 F_b
//  - float4 gmem staging in gload / k_pair_pre / k_eig / means
// ---------------------------------------------------------------------------

#define LD 65
#define SLOT (64 * LD)
#define TAIL 384
#define MAXSWEEP 10
#define JTOL1S 1e-5f
#define NSMAX 13

// --- scratch ---------------------------------------------------------------
__device__ float g_abuf[16777216];   // bary matrices
__device__ float g_fbuf[16777216];   // bary factors
__device__ float g_lbuf[16777216];   // log matrices
__device__ float g_cbuf[16777216];   // eig factor (in/out of k_eig)
__device__ float g_glbuf[16777216];  // per-pair dense L_G
__device__ float g_lam[262144];      // 4096 x 64 eigenvalues
__device__ float g_part[32768];
__device__ float g_w01[2];
__device__ float g_G0[4096];
__device__ float g_Sbar[4096];
__device__ float g_L0[4096];
__device__ float g_Li0[4096];
__device__ float g_T[4096];

// ---------------------------------------------------------------------------
__device__ float block_sum(float v, float* red) {
    const int tid = threadIdx.x;
    #pragma unroll
    for (int o = 16; o > 0; o >>= 1) v += __shfl_xor_sync(0xFFFFFFFFu, v, o);
    __syncthreads();
    if ((tid & 31) == 0) red[tid >> 5] = v;
    __syncthreads();
    if (tid == 0) {
        float s = 0.0f;
        #pragma unroll
        for (int w = 0; w < 8; ++w) s += red[w];
        red[8] = s;
    }
    __syncthreads();
    float r = red[8];
    __syncthreads();
    return r;
}

__device__ float spec_est(const float* A, float* vec, float* red) {
    const int tid = threadIdx.x;
    if (tid < 64) vec[tid] = 1.0f;
    __syncthreads();
    float m = 1.0f;
    for (int it = 0; it < 6; ++it) {
        float y = 0.0f;
        if (tid < 64) {
            #pragma unroll 8
            for (int k = 0; k < 64; ++k) y += A[tid * LD + k] * vec[k];
            float a = fabsf(y);
            #pragma unroll
            for (int o = 16; o > 0; o >>= 1)
                a = fmaxf(a, __shfl_xor_sync(0xFFFFFFFFu, a, o));
            if ((tid & 31) == 0) red[tid >> 5] = a;
        }
        __syncthreads();
        m = fmaxf(red[0], red[1]);
        if (tid < 64) vec[tid] = y / m;
        __syncthreads();
    }
    return m;
}

// ---------------------------------------------------------------------------
// Unscaled LDL^T Cholesky, lower triangle only, row-skipped.
// ---------------------------------------------------------------------------
__device__ void chol_u(float* W) {
    const int tid = threadIdx.x;
    for (int j = 0; j < 64; ++j) {
        float dinv = 1.0f / W[j * LD + j];
        for (int it = j >> 2; it < 16; ++it) {
            int i = tid + it * 256;
            int r = i >> 6, c = i & 63;
            if (r > j && c > j && c <= r)
                W[r * LD + c] -= W[r * LD + j] * W[c * LD + j] * dinv;
        }
        __syncthreads();
    }
}

// dual-matrix fused variant: same barriers, both matrices per step
__device__ void chol_u2(float* W0, float* W1) {
    const int tid = threadIdx.x;
    for (int j = 0; j < 64; ++j) {
        float d0 = 1.0f / W0[j * LD + j];
        float d1 = 1.0f / W1[j * LD + j];
        for (int it = j >> 2; it < 16; ++it) {
            int i = tid + it * 256;
            int r = i >> 6, c = i & 63;
            if (r > j && c > j && c <= r) {
                W0[r * LD + c] -= W0[r * LD + j] * W0[c * LD + j] * d0;
                W1[r * LD + c] -= W1[r * LD + j] * W1[c * LD + j] * d1;
            }
        }
        __syncthreads();
    }
}

// X <- Ltil^{-1} X for LOWER-TRIANGULAR X (upper exactly zero and stays so).
// Live update region at step i: r > i, c <= i.  Row i is final at step i.
__device__ void trsm_left(const float* W, float* X) {
    const int tid = threadIdx.x;
    for (int i = 0; i < 64; ++i) {
        float dinv = 1.0f / W[i * LD + i];
        for (int it = i >> 2; it < 16; ++it) {
            int idx = tid + it * 256;
            int r = idx >> 6, c = idx & 63;
            if (r > i && c <= i)
                X[r * LD + c] -= (W[r * LD + i] * dinv) * X[i * LD + c];
        }
        __syncthreads();
    }
}

// ---------------------------------------------------------------------------
// 64x64 matmuls (256 threads, 4x4 tiles). In-place C==A or C==B is safe.
// ---------------------------------------------------------------------------
__device__ void mm_nn(float* C, const float* A, const float* B) {
    const int t = threadIdx.x;
    const int i0 = (t >> 4) << 2, j0 = (t & 15) << 2;
    float acc[4][4];
    #pragma unroll
    for (int r = 0; r < 4; ++r)
        #pragma unroll
        for (int c = 0; c < 4; ++c) acc[r][c] = 0.0f;
    #pragma unroll 4
    for (int k = 0; k < 64; ++k) {
        float a[4], b[4];
        #pragma unroll
        for (int r = 0; r < 4; ++r) a[r] = A[(i0 + r) * LD + k];
        #pragma unroll
        for (int c = 0; c < 4; ++c) b[c] = B[k * LD + j0 + c];
        #pragma unroll
        for (int r = 0; r < 4; ++r)
            #pragma unroll
            for (int c = 0; c < 4; ++c) acc[r][c] += a[r] * b[c];
    }
    __syncthreads();
    #pragma unroll
    for (int r = 0; r < 4; ++r)
        #pragma unroll
        for (int c = 0; c < 4; ++c) C[(i0 + r) * LD + j0 + c] = acc[r][c];
    __syncthreads();
}

// C = A * B with A LOWER-TRIANGULAR (upper entries exactly zero).
// Per-thread k-bound i0+4 (uniform per thread). In-place on B is safe.
__device__ void mm_ltA(float* C, const float* A, const float* B) {
    const int t = threadIdx.x;
    const int i0 = (t >> 4) << 2, j0 = (t & 15) << 2;
    const int kmax = i0 + 4;
    float acc[4][4];
    #pragma unroll
    for (int r = 0; r < 4; ++r)
        #pragma unroll
        for (int c = 0; c < 4; ++c) acc[r][c] = 0.0f;
    #pragma unroll 4
    for (int k = 0; k < kmax; ++k) {
        float a[4], b[4];
        #pragma unroll
        for (int r = 0; r < 4; ++r) a[r] = A[(i0 + r) * LD + k];
        #pragma unroll
        for (int c = 0; c < 4; ++c) b[c] = B[k * LD + j0 + c];
        #pragma unroll
        for (int r = 0; r < 4; ++r)
            #pragma unroll
            for (int c = 0; c < 4; ++c) acc[r][c] += a[r] * b[c];
    }
    __syncthreads();
    #pragma unroll
    for (int r = 0; r < 4; ++r)
        #pragma unroll
        for (int c = 0; c < 4; ++c) C[(i0 + r) * LD + j0 + c] = acc[r][c];
    __syncthreads();
}

__device__ void mm_nt(float* C, const float* A, const float* B) {
    const int t = threadIdx.x;
    const int i0 = (t >> 4) << 2, j0 = (t & 15) << 2;
    float acc[4][4];
    #pragma unroll
    for (int r = 0; r < 4; ++r)
        #pragma unroll
        for (int c = 0; c < 4; ++c) acc[r][c] = 0.0f;
    #pragma unroll 4
    for (int k = 0; k < 64; ++k) {
        float a[4], b[4];
        #pragma unroll
        for (int r = 0; r < 4; ++r) a[r] = A[(i0 + r) * LD + k];
        #pragma unroll
        for (int c = 0; c < 4; ++c) b[c] = B[(j0 + c) * LD + k];
        #pragma unroll
        for (int r = 0; r < 4; ++r)
            #pragma unroll
            for (int c = 0; c < 4; ++c) acc[r][c] += a[r] * b[c];
    }
    __syncthreads();
    #pragma unroll
    for (int r = 0; r < 4; ++r)
        #pragma unroll
        for (int c = 0; c < 4; ++c) C[(i0 + r) * LD + j0 + c] = acc[r][c];
    __syncthreads();
}

__device__ void mm_nn_g(float* Cg, const float* A, const float* B) {
    const int t = threadIdx.x;
    const int i0 = (t >> 4) << 2, j0 = (t & 15) << 2;
    float acc[4][4];
    #pragma unroll
    for (int r = 0; r < 4; ++r)
        #pragma unroll
        for (int c = 0; c < 4; ++c) acc[r][c] = 0.0f;
    #pragma unroll 4
    for (int k = 0; k < 64; ++k) {
        float a[4], b[4];
        #pragma unroll
        for (int r = 0; r < 4; ++r) a[r] = A[(i0 + r) * LD + k];
        #pragma unroll
        for (int c = 0; c < 4; ++c) b[c] = B[k * LD + j0 + c];
        #pragma unroll
        for (int r = 0; r < 4; ++r)
            #pragma unroll
            for (int c = 0; c < 4; ++c) acc[r][c] += a[r] * b[c];
    }
    #pragma unroll
    for (int r = 0; r < 4; ++r)
        #pragma unroll
        for (int c = 0; c < 4; ++c) Cg[(i0 + r) * 64 + j0 + c] = acc[r][c];
    __syncthreads();
}

__device__ void mm_nt_g(float* Cg, const float* A, const float* B) {
    const int t = threadIdx.x;
    const int i0 = (t >> 4) << 2, j0 = (t & 15) << 2;
    float acc[4][4];
    #pragma unroll
    for (int r = 0; r < 4; ++r)
        #pragma unroll
        for (int c = 0; c < 4; ++c) acc[r][c] = 0.0f;
    #pragma unroll 4
    for (int k = 0; k < 64; ++k) {
        float a[4], b[4];
        #pragma unroll
        for (int r = 0; r < 4; ++r) a[r] = A[(i0 + r) * LD + k];
        #pragma unroll
        for (int c = 0; c < 4; ++c) b[c] = B[(j0 + c) * LD + k];
        #pragma unroll
        for (int r = 0; r < 4; ++r)
            #pragma unroll
            for (int c = 0; c < 4; ++c) acc[r][c] += a[r] * b[c];
    }
    #pragma unroll
    for (int r = 0; r < 4; ++r)
        #pragma unroll
        for (int c = 0; c < 4; ++c) Cg[(i0 + r) * 64 + j0 + c] = acc[r][c];
    __syncthreads();
}

// Cg(gmem) = V diag(f) V^T
__device__ void mm_recon_g(float* Cg, const float* V, const float* f) {
    const int t = threadIdx.x;
    const int i0 = (t >> 4) << 2, j0 = (t & 15) << 2;
    float acc[4][4];
    #pragma unroll
    for (int r = 0; r < 4; ++r)
        #pragma unroll
        for (int c = 0; c < 4; ++c) acc[r][c] = 0.0f;
    #pragma unroll 4
    for (int k = 0; k < 64; ++k) {
        float fk = f[k];
        float a[4], b[4];
        #pragma unroll
        for (int r = 0; r < 4; ++r) a[r] = V[(i0 + r) * LD + k] * fk;
        #pragma unroll
        for (int c = 0; c < 4; ++c) b[c] = V[(j0 + c) * LD + k];
        #pragma unroll
        for (int r = 0; r < 4; ++r)
            #pragma unroll
            for (int c = 0; c < 4; ++c) acc[r][c] += a[r] * b[c];
    }
    #pragma unroll
    for (int r = 0; r < 4; ++r)
        #pragma unroll
        for (int c = 0; c < 4; ++c) Cg[(i0 + r) * 64 + j0 + c] = acc[r][c];
    __syncthreads();
}

// float4 gmem -> padded smem
__device__ void gload(float* M, const float* g) {
    for (int i = threadIdx.x * 4; i < 4096; i += 1024) {
        float4 v = *(const float4*)(g + i);
        float* p = M + (i >> 6) * LD + (i & 63);
        p[0] = v.x; p[1] = v.y; p[2] = v.z; p[3] = v.w;
    }
    __syncthreads();
}

// ---------------------------------------------------------------------------
// NS + sexpm (k_bary only)
// ---------------------------------------------------------------------------
__device__ void ns_sqrt(float* Y, float* Z, float* T, float* red) {
    const int tid = threadIdx.x;
    for (int it = 0; it < NSMAX; ++it) {
        mm_nn(T, Z, Y);
        float mx = 0.0f;
        for (int i = tid; i < 4096; i += 256) {
            int r = i >> 6, c = i & 63;
            float v = T[r * LD + c];
            float t = ((r == c) ? 1.5f : 0.0f) - 0.5f * v;
            T[r * LD + c] = t;
            mx = fmaxf(mx, fabsf(t - ((r == c) ? 1.0f : 0.0f)));
        }
        __syncthreads();
        #pragma unroll
        for (int o = 16; o > 0; o >>= 1)
            mx = fmaxf(mx, __shfl_xor_sync(0xFFFFFFFFu, mx, o));
        if ((tid & 31) == 0) red[tid >> 5] = mx;
        __syncthreads();
        if (tid == 0) {
            float g = 0.0f;
            #pragma unroll
            for (int w = 0; w < 8; ++w) g = fmaxf(g, red[w]);
            red[8] = g;
        }
        __syncthreads();
        float g = red[8];
        __syncthreads();
        if (g < 3e-8f) break;
        mm_nn(Y, Y, T);
        mm_nn(Z, T, Z);
    }
}

__device__ void sexpm(float* B, float* Q, float* T, float* red) {
    const int tid = threadIdx.x;
    float s2 = 0.0f;
    for (int i = tid; i < 4096; i += 256) {
        float v = B[(i >> 6) * LD + (i & 63)];
        s2 += v * v;
    }
    float fn = sqrtf(block_sum(s2, red));
    int s = 0; float f = fn;
    while (f > 0.5f && s < 40) { f *= 0.5f; ++s; }
    float scale = ldexpf(1.0f, -s);
    for (int i = tid; i < 4096; i += 256)
        B[(i >> 6) * LD + (i & 63)] *= scale;
    __syncthreads();
    for (int i = tid; i < 4096; i += 256) {
        int r = i >> 6, c = i & 63;
        Q[r * LD + c] = ((r == c) ? 1.0f : 0.0f) + 0.1f * B[r * LD + c];
    }
    __syncthreads();
    for (int k = 9; k >= 1; --k) {
        mm_nn(T, B, Q);
        float inv = 1.0f / (float)k;
        for (int i = tid; i < 4096; i += 256) {
            int r = i >> 6, c = i & 63;
            Q[r * LD + c] = ((r == c) ? 1.0f : 0.0f) + inv * T[r * LD + c];
        }
        __syncthreads();
    }
    for (int i = 0; i < s; ++i) mm_nn(Q, Q, Q);
}

// ---------------------------------------------------------------------------
__global__ void k_softmax(const float* __restrict__ wv) {
    float a = wv[0], b = wv[1];
    float m = fmaxf(a, b);
    float ea = expf(a - m), eb = expf(b - m);
    float inv = 1.0f / (ea + eb);
    g_w01[0] = ea * inv;
    g_w01[1] = eb * inv;
}

// ---------------------------------------------------------------------------
// k_eig: register-resident one-sided Jacobi, circle-method positions.
// ---------------------------------------------------------------------------
__global__ void __launch_bounds__(64) k_eig() {
    __shared__ float sm[64 * 65];
    __shared__ float nrm[64];
    __shared__ float cbuf[32];
    __shared__ float sbuf[32];
    __shared__ float flag;
    const int r = threadIdx.x;
    const int m = blockIdx.x;
    float* gb = g_cbuf + (size_t)m * 4096;

    // float4 coalesced load into padded smem
    #pragma unroll
    for (int it = 0; it < 16; ++it) {
        int idx = it * 256 + r * 4;
        float4 v = *(const float4*)(gb + idx);
        float* p = sm + (idx >> 6) * 65 + (idx & 63);
        p[0] = v.x; p[1] = v.y; p[2] = v.z; p[3] = v.w;
    }
    __syncthreads();
    {
        float s = 0.0f;
        #pragma unroll
        for (int a = 0; a < 64; ++a) { float v = sm[a * 65 + r]; s += v * v; }
        nrm[r] = s;
    }
    float w[64];
    #pragma unroll
    for (int j = 0; j < 64; ++j) w[j] = sm[r * 65 + j];
    __syncthreads();

    #pragma unroll 1
    for (int sw = 0; sw < MAXSWEEP; ++sw) {
        float gacc = 0.0f;
        #pragma unroll
        for (int rnd = 0; rnd < 63; ++rnd) {
            sm[0 * 65 + r] = w[0] * w[63];
            #pragma unroll
            for (int k = 1; k < 32; ++k)
                sm[k * 65 + r] = w[k] * w[63 - k];
            __syncthreads();
            if (r < 32) {
                float gam = 0.0f;
                #pragma unroll
                for (int a = 0; a < 64; ++a) gam += sm[r * 65 + a];
                const int A = (r == 0) ? 0 : r;
                const int B = (r == 0) ? 63 : 63 - r;
                float al = nrm[A], be = nrm[B];
                float c = 1.0f, s = 0.0f;
                if (fabsf(gam) > 1e-37f) {
                    float tau = (be - al) / (2.0f * gam);
                    float t = copysignf(1.0f, tau) /
                              (fabsf(tau) + sqrtf(1.0f + tau * tau));
                    c = rsqrtf(1.0f + t * t);
                    s = t * c;
                    float cs = c * s;
                    float nal = c * c * al - 2.0f * cs * gam + s * s * be;
                    float nbe = s * s * al + 2.0f * cs * gam + c * c * be;
                    al = nal; be = nbe;
                }
                __syncwarp();
                const int sA = (r == 0) ? 0 : r + 1;
                const int sB = (r == 0) ? 1 : 64 - r;
                nrm[sA] = al;
                nrm[sB] = be;
                cbuf[r] = c; sbuf[r] = s;
                gacc += gam * gam;
            }
            __syncthreads();
            {
                float c0 = cbuf[0], s0 = sbuf[0];
                float vp = w[0], vq = w[63];
                w[0]  = c0 * vp - s0 * vq;
                w[63] = s0 * vp + c0 * vq;
            }
            #pragma unroll
            for (int k = 1; k < 32; ++k) {
                float c = cbuf[k], s = sbuf[k];
                float vp = w[k], vq = w[63 - k];
                w[k]      = c * vp - s * vq;
                w[63 - k] = s * vp + c * vq;
            }
            {
                float tmp = w[63];
                #pragma unroll
                for (int i = 62; i >= 1; --i) w[i + 1] = w[i];
                w[1] = tmp;
            }
        }
        if (r < 32) {
            float tot = gacc;
            float d = nrm[r] * nrm[r] + nrm[r + 32] * nrm[r + 32];
            #pragma unroll
            for (int o = 16; o > 0; o >>= 1) {
                tot += __shfl_xor_sync(0xFFFFFFFFu, tot, o);
                d   += __shfl_xor_sync(0xFFFFFFFFu, d, o);
            }
            if (r == 0) flag = (tot <= JTOL1S * d + 1e-30f) ? 1.0f : 0.0f;
        }
        __syncthreads();
        if (flag != 0.0f) break;
    }

    #pragma unroll
    for (int j = 0; j < 64; ++j) sm[r * 65 + j] = w[j];
    __syncthreads();
    {
        float s = 0.0f;
        #pragma unroll
        for (int a = 0; a < 64; ++a) { float v = sm[a * 65 + r]; s += v * v; }
        g_lam[(size_t)m * 64 + r] = s;
    }
    #pragma unroll
    for (int it = 0; it < 16; ++it) {
        int idx = it * 256 + r * 4;
        const float* p = sm + (idx >> 6) * 65 + (idx & 63);
        float4 v; v.x = p[0]; v.y = p[1]; v.z = p[2]; v.w = p[3];
        *(float4*)(gb + idx) = v;
    }
}

// ---------------------------------------------------------------------------
// k_pair_pre: dual chol(G, X0), trsm -> F_c (g_cbuf) and dense L_G (g_glbuf)
// ---------------------------------------------------------------------------
__global__ void __launch_bounds__(256, 4) k_pair_pre(const float* __restrict__ x) {
    extern __shared__ float sm[];
    float* s0 = sm;               // G -> cholG
    float* s1 = sm + SLOT;        // X0 -> cholX -> F_c
    float* fv  = sm + 2 * SLOT;   // 64
    float* vec = fv + 64;         // 64
    const int tid = threadIdx.x;
    const int b  = blockIdx.x;
    const int nb = b >> 3, pp = b & 7;
    const int c0 = (pp & 1) + ((pp >> 1) << 2);
    const float* X0 = x + (size_t)(nb * 16 + c0) * 4096;
    const float* X1 = X0 + 2 * 4096;
    const float w0 = g_w01[0], w1 = g_w01[1];

    for (int i = tid * 4; i < 4096; i += 1024) {
        float4 v0 = *(const float4*)(X0 + i);
        float4 v1 = *(const float4*)(X1 + i);
        float* p0 = s0 + (i >> 6) * LD + (i & 63);
        float* p1 = s1 + (i >> 6) * LD + (i & 63);
        p0[0] = w0 * v0.x + w1 * v1.x;
        p0[1] = w0 * v0.y + w1 * v1.y;
        p0[2] = w0 * v0.z + w1 * v1.z;
        p0[3] = w0 * v0.w + w1 * v1.w;
        p1[0] = v0.x; p1[1] = v0.y; p1[2] = v0.z; p1[3] = v0.w;
    }
    __syncthreads();
    chol_u2(s0, s1);              // both factorizations, shared barriers
    if (tid < 64) fv[tid] = s1[tid * 66];
    __syncthreads();
    for (int i = tid; i < 4096; i += 256) {
        int r = i >> 6, c = i & 63;
        float d = fmaxf(fv[c], 1e-30f);
        float v = (c < r) ? s1[r * LD + c] * rsqrtf(d)
                          : ((c == r) ? sqrtf(d) : 0.0f);
        s1[r * LD + c] = v;                    // Lx (upper zeroed)
    }
    __syncthreads();
    trsm_left(s0, s1);                         // Ltil_G^{-1} Lx (stays lower)
    if (tid < 64) vec[tid] = rsqrtf(fmaxf(s0[tid * 66], 1e-30f));
    __syncthreads();
    for (int i = tid * 4; i < 4096; i += 1024) {
        int r = i >> 6, cb = i & 63;
        const float* p1 = s1 + r * LD + cb;
        float4 fc, lg;
        float rv = vec[r];
        fc.x = p1[0] * rv; fc.y = p1[1] * rv;
        fc.z = p1[2] * rv; fc.w = p1[3] * rv;
        #pragma unroll
        for (int j = 0; j < 4; ++j) {
            int c = cb + j;
            float d = fmaxf(s0[c * 66], 1e-30f);
            float lv = (c < r) ? s0[r * LD + c] * rsqrtf(d)
                               : ((c == r) ? sqrtf(d) : 0.0f);
            ((float*)&lg)[j] = lv;
        }
        *(float4*)(g_cbuf  + (size_t)b * 4096 + i) = fc;
        *(float4*)(g_glbuf + (size_t)b * 4096 + i) = lg;
    }
}

// ---------------------------------------------------------------------------
// k_pair_post: F_b = L_G W diag(sqrt(g/l)); bary = F_b F_b^T
// ---------------------------------------------------------------------------
__global__ void __launch_bounds__(256, 4) k_pair_post() {
    extern __shared__ float sm[];
    float* s0 = sm;               // L_G (lower-tri, upper zero)
    float* s1 = sm + SLOT;        // W -> F_b
    float* fv = sm + 2 * SLOT;    // 64
    const int tid = threadIdx.x;
    const int b = blockIdx.x;
    const float w0 = g_w01[0], w1 = g_w01[1];
    gload(s0, g_glbuf + (size_t)b * 4096);
    gload(s1, g_cbuf + (size_t)b * 4096);
    if (tid < 64) {
        float a = fmaxf(g_lam[(size_t)b * 64 + tid], 1e-12f);
        float bb = fmaxf((1.0f - w0 * a) / w1, 1e-12f);
        float g = expf(w0 * logf(a) + w1 * logf(bb));
        fv[tid] = sqrtf(g / a);
    }
    __syncthreads();
    for (int i = tid; i < 4096; i += 256) {
        int r = i >> 6, c = i & 63;
        s1[r * LD + c] *= fv[c];
    }
    __syncthreads();
    mm_ltA(s1, s0, s1);           // F_b = L_G * W' (triangular A, in-place)
    float* fb = g_fbuf + (size_t)b * 4096;
    for (int i = tid * 4; i < 4096; i += 1024) {
        const float* p = s1 + (i >> 6) * LD + (i & 63);
        float4 v; v.x = p[0]; v.y = p[1]; v.z = p[2]; v.w = p[3];
        *(float4*)(fb + i) = v;
    }
    mm_nt_g(g_abuf + (size_t)b * 4096, s1, s1);
}

// ---------------------------------------------------------------------------
// means: 2-stage deterministic (stage 1 float4)
// ---------------------------------------------------------------------------
__global__ void k_meanA_s1() {
    const int e = (blockIdx.x * 256 + threadIdx.x) * 4;
    const int m0 = blockIdx.y * 512;
    float4 s = make_float4(0.f, 0.f, 0.f, 0.f);
    #pragma unroll 4
    for (int m = 0; m < 512; ++m) {
        float4 v = *(const float4*)(g_abuf + (size_t)(m0 + m) * 4096 + e);
        s.x += v.x; s.y += v.y; s.z += v.z; s.w += v.w;
    }
    *(float4*)(g_part + blockIdx.y * 4096 + e) = s;
}
__global__ void k_meanA_s2() {
    const int e = blockIdx.x * 256 + threadIdx.x;
    float s = 0.0f;
    #pragma unroll
    for (int w = 0; w < 8; ++w) s += g_part[w * 4096 + e];
    g_G0[e] = s * (1.0f / 4096.0f);
}
__global__ void k_meanL_s1() {
    const int e = (blockIdx.x * 256 + threadIdx.x) * 4;
    const int m0 = blockIdx.y * 512;
    float4 s = make_float4(0.f, 0.f, 0.f, 0.f);
    #pragma unroll 4
    for (int m = 0; m < 512; ++m) {
        float4 v = *(const float4*)(g_lbuf + (size_t)(m0 + m) * 4096 + e);
        s.x += v.x; s.y += v.y; s.z += v.z; s.w += v.w;
    }
    *(float4*)(g_part + blockIdx.y * 4096 + e) = s;
}
__global__ void k_meanL_s2() {
    const int e = blockIdx.x * 256 + threadIdx.x;
    float s = 0.0f;
    #pragma unroll
    for (int w = 0; w < 8; ++w) s += g_part[w * 4096 + e];
    g_Sbar[e] = s * (1.0f / 4096.0f);
}

// ---------------------------------------------------------------------------
// K4: Cholesky of G0 -> dense L0 and L0^{-1} (single block)
// ---------------------------------------------------------------------------
__global__ void __launch_bounds__(256, 1) k_g0() {
    extern __shared__ float sm[];
    float* s0 = sm;
    float* s1 = sm + SLOT;
    const int tid = threadIdx.x;
    gload(s0, g_G0);
    chol_u(s0);
    for (int i = tid; i < 4096; i += 256) {
        int r = i >> 6, c = i & 63;
        float d = fmaxf(s0[c * 66], 1e-30f);
        float v = (c < r) ? s0[r * LD + c] * rsqrtf(d)
                          : ((c == r) ? sqrtf(d) : 0.0f);
        g_L0[i] = v;
        s1[r * LD + c] = (r == c) ? 1.0f : 0.0f;
    }
    __syncthreads();
    trsm_left(s0, s1);            // identity is lower-tri; result lower-tri
    for (int i = tid; i < 4096; i += 256) {
        int r = i >> 6, c = i & 63;
        g_Li0[i] = rsqrtf(fmaxf(s0[r * 66], 1e-30f)) * s1[r * LD + c];
    }
}

// ---------------------------------------------------------------------------
// k_bn1_pre: Fm = Li0 F_b -> g_cbuf  (Li0 lower-triangular)
// ---------------------------------------------------------------------------
__global__ void __launch_bounds__(256, 4) k_bn1_pre() {
    extern __shared__ float sm[];
    float* s0 = sm;
    float* s1 = sm + SLOT;
    const int tid = threadIdx.x;
    const int m = blockIdx.x;
    gload(s0, g_Li0);
    gload(s1, g_fbuf + (size_t)m * 4096);
    mm_ltA(s1, s0, s1);           // triangular A, in-place
    for (int i = tid * 4; i < 4096; i += 1024) {
        const float* p = s1 + (i >> 6) * LD + (i & 63);
        float4 v; v.x = p[0]; v.y = p[1]; v.z = p[2]; v.w = p[3];
        *(float4*)(g_cbuf + (size_t)m * 4096 + i) = v;
    }
}

// ---------------------------------------------------------------------------
// k_bn1_post: L_m = W diag(log l / l) W^T -> g_lbuf
// ---------------------------------------------------------------------------
__global__ void __launch_bounds__(256, 4) k_bn1_post() {
    extern __shared__ float sm[];
    float* s1 = sm;
    float* fv = sm + SLOT;
    const int tid = threadIdx.x;
    const int m = blockIdx.x;
    gload(s1, g_cbuf + (size_t)m * 4096);
    if (tid < 64) {
        float l = fmaxf(g_lam[(size_t)m * 64 + tid], 1e-12f);
        fv[tid] = logf(l) / l;
    }
    __syncthreads();
    mm_recon_g(g_lbuf + (size_t)m * 4096, s1, fv);
}

// ---------------------------------------------------------------------------
// K7: bary = L0 expm(Sbar) L0^T; T = bnw^{1/2} @ bary^{-1/2}. single block.
// ---------------------------------------------------------------------------
__global__ void __launch_bounds__(256, 1) k_bary(const float* __restrict__ bnw) {
    extern __shared__ float sm[];
    float* s0 = sm;
    float* s1 = sm + SLOT;
    float* s2 = sm + 2 * SLOT;
    float* s3 = sm + 3 * SLOT;
    float* red = sm + 4 * SLOT;
    float* vec = red + 24;
    const int tid = threadIdx.x;

    gload(s0, g_Sbar);
    sexpm(s0, s1, s2, red);
    gload(s0, g_L0);
    mm_nn(s2, s0, s1);
    mm_nt(s1, s2, s0);               // bary
    float lam = spec_est(s1, vec, red);
    float csc = 1.15f * lam, ic = 1.0f / csc;
    for (int i = tid; i < 4096; i += 256) {
        int r = i >> 6, c = i & 63;
        s1[r * LD + c] *= ic;
        s3[r * LD + c] = (r == c) ? 1.0f : 0.0f;
    }
    __syncthreads();
    ns_sqrt(s1, s3, s2, red);
    float irc = rsqrtf(csc);
    for (int i = tid; i < 4096; i += 256) {
        int r = i >> 6, c = i & 63;
        s3[r * LD + c] *= irc;       // bary^{-1/2}
    }
    __syncthreads();
    gload(s0, bnw);
    float lam2 = spec_est(s0, vec, red);
    float c2 = 1.15f * lam2, ic2 = 1.0f / c2;
    for (int i = tid; i < 4096; i += 256) {
        int r = i >> 6, c = i & 63;
        s0[r * LD + c] *= ic2;
        s1[r * LD + c] = (r == c) ? 1.0f : 0.0f;
    }
    __syncthreads();
    ns_sqrt(s0, s1, s2, red);
    float rc2 = sqrtf(c2);
    for (int i = tid; i < 4096; i += 256) {
        int r = i >> 6, c = i & 63;
        s0[r * LD + c] *= rc2;       // Ws
    }
    __syncthreads();
    mm_nn_g(g_T, s0, s3);            // T
}

// ---------------------------------------------------------------------------
// K8: out = T M T^T
// ---------------------------------------------------------------------------
__global__ void __launch_bounds__(256, 4) k_out(float* __restrict__ out) {
    extern __shared__ float sm[];
    float* MG = sm;
    float* MA = sm + SLOT;
    float* MT = sm + 2 * SLOT;
    const int m = blockIdx.x;
    gload(MG, g_T);
    gload(MA, g_abuf + (size_t)m * 4096);
    mm_nn(MT, MG, MA);
    mm_nt_g(out + (size_t)m * 4096, MT, MG);
}

// ---------------------------------------------------------------------------
extern "C" void kernel_launch(void* const* d_in, const int* in_sizes, int n_in,
                              void* d_out, int out_size) {
    const float* x   = (const float*)d_in[0];
    const float* w1  = (const float*)d_in[1];
    const float* bnw = (const float*)d_in[2];
    float* out = (float*)d_out;

    const int sm4t = (4 * SLOT + TAIL) * (int)sizeof(float);
    const int sm3  = (3 * SLOT) * (int)sizeof(float);
    const int sm2t = (2 * SLOT + TAIL) * (int)sizeof(float);
    const int sm2  = (2 * SLOT) * (int)sizeof(float);

    cudaFuncSetAttribute(k_pair_pre,  cudaFuncAttributeMaxDynamicSharedMemorySize, sm2t);
    cudaFuncSetAttribute(k_pair_post, cudaFuncAttributeMaxDynamicSharedMemorySize, sm2t);
    cudaFuncSetAttribute(k_g0,        cudaFuncAttributeMaxDynamicSharedMemorySize, sm2);
    cudaFuncSetAttribute(k_bn1_pre,   cudaFuncAttributeMaxDynamicSharedMemorySize, sm2);
    cudaFuncSetAttribute(k_bn1_post,  cudaFuncAttributeMaxDynamicSharedMemorySize, sm2t);
    cudaFuncSetAttribute(k_bary,      cudaFuncAttributeMaxDynamicSharedMemorySize, sm4t);
    cudaFuncSetAttribute(k_out,       cudaFuncAttributeMaxDynamicSharedMemorySize, sm3);

    k_softmax<<<1, 1>>>(w1);
    k_pair_pre<<<4096, 256, sm2t>>>(x);
    k_eig<<<4096, 64>>>();
    k_pair_post<<<4096, 256, sm2t>>>();
    k_meanA_s1<<<dim3(4, 8), 256>>>();
    k_meanA_s2<<<16, 256>>>();
    k_g0<<<1, 256, sm2>>>();
    k_bn1_pre<<<4096, 256, sm2>>>();
    k_eig<<<4096, 64>>>();
    k_bn1_post<<<4096, 256, sm2t>>>();
    k_meanL_s1<<<dim3(4, 8), 256>>>();
    k_meanL_s2<<<16, 256>>>();
    k_bary<<<1, 256, sm4t>>>(bnw);
    k_out<<<4096, 256, sm3>>>(out);
    (void)in_sizes; (void)n_in; (void)out_size;
}

// round 15
// speedup vs baseline: 1.0167x; 1.0167x over previous
#include <cuda_runtime.h>
#include <math.h>

// ---------------------------------------------------------------------------
// DiMap SPD pipeline, round 14.
// R13 + restructured k_eig:
//  - dot-product reduction split across both warps (32-add chains, no idle warp)
//  - two matrices per block (128 threads), shared barriers
// JTOL1S stays 1e-5 (rel_err ~2.7e-5). All other kernels identical to R13.
// ---------------------------------------------------------------------------

#define LD 65
#define SLOT (64 * LD)
#define TAIL 384
#define MAXSWEEP 10
#define JTOL1S 1e-5f
#define NSMAX 13

// --- scratch ---------------------------------------------------------------
__device__ float g_abuf[16777216];   // bary matrices
__device__ float g_fbuf[16777216];   // bary factors
__device__ float g_lbuf[16777216];   // log matrices
__device__ float g_cbuf[16777216];   // eig factor (in/out of k_eig)
__device__ float g_glbuf[16777216];  // per-pair dense L_G
__device__ float g_lam[262144];      // 4096 x 64 eigenvalues
__device__ float g_part[32768];
__device__ float g_w01[2];
__device__ float g_G0[4096];
__device__ float g_Sbar[4096];
__device__ float g_L0[4096];
__device__ float g_Li0[4096];
__device__ float g_T[4096];

// ---------------------------------------------------------------------------
__device__ float block_sum(float v, float* red) {
    const int tid = threadIdx.x;
    #pragma unroll
    for (int o = 16; o > 0; o >>= 1) v += __shfl_xor_sync(0xFFFFFFFFu, v, o);
    __syncthreads();
    if ((tid & 31) == 0) red[tid >> 5] = v;
    __syncthreads();
    if (tid == 0) {
        float s = 0.0f;
        #pragma unroll
        for (int w = 0; w < 8; ++w) s += red[w];
        red[8] = s;
    }
    __syncthreads();
    float r = red[8];
    __syncthreads();
    return r;
}

__device__ float spec_est(const float* A, float* vec, float* red) {
    const int tid = threadIdx.x;
    if (tid < 64) vec[tid] = 1.0f;
    __syncthreads();
    float m = 1.0f;
    for (int it = 0; it < 6; ++it) {
        float y = 0.0f;
        if (tid < 64) {
            #pragma unroll 8
            for (int k = 0; k < 64; ++k) y += A[tid * LD + k] * vec[k];
            float a = fabsf(y);
            #pragma unroll
            for (int o = 16; o > 0; o >>= 1)
                a = fmaxf(a, __shfl_xor_sync(0xFFFFFFFFu, a, o));
            if ((tid & 31) == 0) red[tid >> 5] = a;
        }
        __syncthreads();
        m = fmaxf(red[0], red[1]);
        if (tid < 64) vec[tid] = y / m;
        __syncthreads();
    }
    return m;
}

// ---------------------------------------------------------------------------
// Unscaled LDL^T Cholesky, lower triangle only, row-skipped.
// ---------------------------------------------------------------------------
__device__ void chol_u(float* W) {
    const int tid = threadIdx.x;
    for (int j = 0; j < 64; ++j) {
        float dinv = 1.0f / W[j * LD + j];
        for (int it = j >> 2; it < 16; ++it) {
            int i = tid + it * 256;
            int r = i >> 6, c = i & 63;
            if (r > j && c > j && c <= r)
                W[r * LD + c] -= W[r * LD + j] * W[c * LD + j] * dinv;
        }
        __syncthreads();
    }
}

// dual-matrix fused variant: same barriers, both matrices per step
__device__ void chol_u2(float* W0, float* W1) {
    const int tid = threadIdx.x;
    for (int j = 0; j < 64; ++j) {
        float d0 = 1.0f / W0[j * LD + j];
        float d1 = 1.0f / W1[j * LD + j];
        for (int it = j >> 2; it < 16; ++it) {
            int i = tid + it * 256;
            int r = i >> 6, c = i & 63;
            if (r > j && c > j && c <= r) {
                W0[r * LD + c] -= W0[r * LD + j] * W0[c * LD + j] * d0;
                W1[r * LD + c] -= W1[r * LD + j] * W1[c * LD + j] * d1;
            }
        }
        __syncthreads();
    }
}

// X <- Ltil^{-1} X for LOWER-TRIANGULAR X (upper exactly zero and stays so).
__device__ void trsm_left(const float* W, float* X) {
    const int tid = threadIdx.x;
    for (int i = 0; i < 64; ++i) {
        float dinv = 1.0f / W[i * LD + i];
        for (int it = i >> 2; it < 16; ++it) {
            int idx = tid + it * 256;
            int r = idx >> 6, c = idx & 63;
            if (r > i && c <= i)
                X[r * LD + c] -= (W[r * LD + i] * dinv) * X[i * LD + c];
        }
        __syncthreads();
    }
}

// ---------------------------------------------------------------------------
// 64x64 matmuls (256 threads, 4x4 tiles). In-place C==A or C==B is safe.
// ---------------------------------------------------------------------------
__device__ void mm_nn(float* C, const float* A, const float* B) {
    const int t = threadIdx.x;
    const int i0 = (t >> 4) << 2, j0 = (t & 15) << 2;
    float acc[4][4];
    #pragma unroll
    for (int r = 0; r < 4; ++r)
        #pragma unroll
        for (int c = 0; c < 4; ++c) acc[r][c] = 0.0f;
    #pragma unroll 4
    for (int k = 0; k < 64; ++k) {
        float a[4], b[4];
        #pragma unroll
        for (int r = 0; r < 4; ++r) a[r] = A[(i0 + r) * LD + k];
        #pragma unroll
        for (int c = 0; c < 4; ++c) b[c] = B[k * LD + j0 + c];
        #pragma unroll
        for (int r = 0; r < 4; ++r)
            #pragma unroll
            for (int c = 0; c < 4; ++c) acc[r][c] += a[r] * b[c];
    }
    __syncthreads();
    #pragma unroll
    for (int r = 0; r < 4; ++r)
        #pragma unroll
        for (int c = 0; c < 4; ++c) C[(i0 + r) * LD + j0 + c] = acc[r][c];
    __syncthreads();
}

// C = A * B with A LOWER-TRIANGULAR (upper entries exactly zero).
__device__ void mm_ltA(float* C, const float* A, const float* B) {
    const int t = threadIdx.x;
    const int i0 = (t >> 4) << 2, j0 = (t & 15) << 2;
    const int kmax = i0 + 4;
    float acc[4][4];
    #pragma unroll
    for (int r = 0; r < 4; ++r)
        #pragma unroll
        for (int c = 0; c < 4; ++c) acc[r][c] = 0.0f;
    #pragma unroll 4
    for (int k = 0; k < kmax; ++k) {
        float a[4], b[4];
        #pragma unroll
        for (int r = 0; r < 4; ++r) a[r] = A[(i0 + r) * LD + k];
        #pragma unroll
        for (int c = 0; c < 4; ++c) b[c] = B[k * LD + j0 + c];
        #pragma unroll
        for (int r = 0; r < 4; ++r)
            #pragma unroll
            for (int c = 0; c < 4; ++c) acc[r][c] += a[r] * b[c];
    }
    __syncthreads();
    #pragma unroll
    for (int r = 0; r < 4; ++r)
        #pragma unroll
        for (int c = 0; c < 4; ++c) C[(i0 + r) * LD + j0 + c] = acc[r][c];
    __syncthreads();
}

__device__ void mm_nt(float* C, const float* A, const float* B) {
    const int t = threadIdx.x;
    const int i0 = (t >> 4) << 2, j0 = (t & 15) << 2;
    float acc[4][4];
    #pragma unroll
    for (int r = 0; r < 4; ++r)
        #pragma unroll
        for (int c = 0; c < 4; ++c) acc[r][c] = 0.0f;
    #pragma unroll 4
    for (int k = 0; k < 64; ++k) {
        float a[4], b[4];
        #pragma unroll
        for (int r = 0; r < 4; ++r) a[r] = A[(i0 + r) * LD + k];
        #pragma unroll
        for (int c = 0; c < 4; ++c) b[c] = B[(j0 + c) * LD + k];
        #pragma unroll
        for (int r = 0; r < 4; ++r)
            #pragma unroll
            for (int c = 0; c < 4; ++c) acc[r][c] += a[r] * b[c];
    }
    __syncthreads();
    #pragma unroll
    for (int r = 0; r < 4; ++r)
        #pragma unroll
        for (int c = 0; c < 4; ++c) C[(i0 + r) * LD + j0 + c] = acc[r][c];
    __syncthreads();
}

__device__ void mm_nn_g(float* Cg, const float* A, const float* B) {
    const int t = threadIdx.x;
    const int i0 = (t >> 4) << 2, j0 = (t & 15) << 2;
    float acc[4][4];
    #pragma unroll
    for (int r = 0; r < 4; ++r)
        #pragma unroll
        for (int c = 0; c < 4; ++c) acc[r][c] = 0.0f;
    #pragma unroll 4
    for (int k = 0; k < 64; ++k) {
        float a[4], b[4];
        #pragma unroll
        for (int r = 0; r < 4; ++r) a[r] = A[(i0 + r) * LD + k];
        #pragma unroll
        for (int c = 0; c < 4; ++c) b[c] = B[k * LD + j0 + c];
        #pragma unroll
        for (int r = 0; r < 4; ++r)
            #pragma unroll
            for (int c = 0; c < 4; ++c) acc[r][c] += a[r] * b[c];
    }
    #pragma unroll
    for (int r = 0; r < 4; ++r)
        #pragma unroll
        for (int c = 0; c < 4; ++c) Cg[(i0 + r) * 64 + j0 + c] = acc[r][c];
    __syncthreads();
}

__device__ void mm_nt_g(float* Cg, const float* A, const float* B) {
    const int t = threadIdx.x;
    const int i0 = (t >> 4) << 2, j0 = (t & 15) << 2;
    float acc[4][4];
    #pragma unroll
    for (int r = 0; r < 4; ++r)
        #pragma unroll
        for (int c = 0; c < 4; ++c) acc[r][c] = 0.0f;
    #pragma unroll 4
    for (int k = 0; k < 64; ++k) {
        float a[4], b[4];
        #pragma unroll
        for (int r = 0; r < 4; ++r) a[r] = A[(i0 + r) * LD + k];
        #pragma unroll
        for (int c = 0; c < 4; ++c) b[c] = B[(j0 + c) * LD + k];
        #pragma unroll
        for (int r = 0; r < 4; ++r)
            #pragma unroll
            for (int c = 0; c < 4; ++c) acc[r][c] += a[r] * b[c];
    }
    #pragma unroll
    for (int r = 0; r < 4; ++r)
        #pragma unroll
        for (int c = 0; c < 4; ++c) Cg[(i0 + r) * 64 + j0 + c] = acc[r][c];
    __syncthreads();
}

// Cg(gmem) = V diag(f) V^T
__device__ void mm_recon_g(float* Cg, const float* V, const float* f) {
    const int t = threadIdx.x;
    const int i0 = (t >> 4) << 2, j0 = (t & 15) << 2;
    float acc[4][4];
    #pragma unroll
    for (int r = 0; r < 4; ++r)
        #pragma unroll
        for (int c = 0; c < 4; ++c) acc[r][c] = 0.0f;
    #pragma unroll 4
    for (int k = 0; k < 64; ++k) {
        float fk = f[k];
        float a[4], b[4];
        #pragma unroll
        for (int r = 0; r < 4; ++r) a[r] = V[(i0 + r) * LD + k] * fk;
        #pragma unroll
        for (int c = 0; c < 4; ++c) b[c] = V[(j0 + c) * LD + k];
        #pragma unroll
        for (int r = 0; r < 4; ++r)
            #pragma unroll
            for (int c = 0; c < 4; ++c) acc[r][c] += a[r] * b[c];
    }
    #pragma unroll
    for (int r = 0; r < 4; ++r)
        #pragma unroll
        for (int c = 0; c < 4; ++c) Cg[(i0 + r) * 64 + j0 + c] = acc[r][c];
    __syncthreads();
}

// float4 gmem -> padded smem
__device__ void gload(float* M, const float* g) {
    for (int i = threadIdx.x * 4; i < 4096; i += 1024) {
        float4 v = *(const float4*)(g + i);
        float* p = M + (i >> 6) * LD + (i & 63);
        p[0] = v.x; p[1] = v.y; p[2] = v.z; p[3] = v.w;
    }
    __syncthreads();
}

// ---------------------------------------------------------------------------
// NS + sexpm (k_bary only)
// ---------------------------------------------------------------------------
__device__ void ns_sqrt(float* Y, float* Z, float* T, float* red) {
    const int tid = threadIdx.x;
    for (int it = 0; it < NSMAX; ++it) {
        mm_nn(T, Z, Y);
        float mx = 0.0f;
        for (int i = tid; i < 4096; i += 256) {
            int r = i >> 6, c = i & 63;
            float v = T[r * LD + c];
            float t = ((r == c) ? 1.5f : 0.0f) - 0.5f * v;
            T[r * LD + c] = t;
            mx = fmaxf(mx, fabsf(t - ((r == c) ? 1.0f : 0.0f)));
        }
        __syncthreads();
        #pragma unroll
        for (int o = 16; o > 0; o >>= 1)
            mx = fmaxf(mx, __shfl_xor_sync(0xFFFFFFFFu, mx, o));
        if ((tid & 31) == 0) red[tid >> 5] = mx;
        __syncthreads();
        if (tid == 0) {
            float g = 0.0f;
            #pragma unroll
            for (int w = 0; w < 8; ++w) g = fmaxf(g, red[w]);
            red[8] = g;
        }
        __syncthreads();
        float g = red[8];
        __syncthreads();
        if (g < 3e-8f) break;
        mm_nn(Y, Y, T);
        mm_nn(Z, T, Z);
    }
}

__device__ void sexpm(float* B, float* Q, float* T, float* red) {
    const int tid = threadIdx.x;
    float s2 = 0.0f;
    for (int i = tid; i < 4096; i += 256) {
        float v = B[(i >> 6) * LD + (i & 63)];
        s2 += v * v;
    }
    float fn = sqrtf(block_sum(s2, red));
    int s = 0; float f = fn;
    while (f > 0.5f && s < 40) { f *= 0.5f; ++s; }
    float scale = ldexpf(1.0f, -s);
    for (int i = tid; i < 4096; i += 256)
        B[(i >> 6) * LD + (i & 63)] *= scale;
    __syncthreads();
    for (int i = tid; i < 4096; i += 256) {
        int r = i >> 6, c = i & 63;
        Q[r * LD + c] = ((r == c) ? 1.0f : 0.0f) + 0.1f * B[r * LD + c];
    }
    __syncthreads();
    for (int k = 9; k >= 1; --k) {
        mm_nn(T, B, Q);
        float inv = 1.0f / (float)k;
        for (int i = tid; i < 4096; i += 256) {
            int r = i >> 6, c = i & 63;
            Q[r * LD + c] = ((r == c) ? 1.0f : 0.0f) + inv * T[r * LD + c];
        }
        __syncthreads();
    }
    for (int i = 0; i < s; ++i) mm_nn(Q, Q, Q);
}

// ---------------------------------------------------------------------------
__global__ void k_softmax(const float* __restrict__ wv) {
    float a = wv[0], b = wv[1];
    float m = fmaxf(a, b);
    float ea = expf(a - m), eb = expf(b - m);
    float inv = 1.0f / (ea + eb);
    g_w01[0] = ea * inv;
    g_w01[1] = eb * inv;
}

// ---------------------------------------------------------------------------
// k_eig: register-resident one-sided Jacobi, circle-method positions.
// TWO matrices per block: warps {0,1} -> matrix A, warps {2,3} -> matrix B.
// Dot reductions split across both warps of each matrix (32-add chains).
// ---------------------------------------------------------------------------
__global__ void __launch_bounds__(128) k_eig() {
    __shared__ float smA[2][64 * 65];
    __shared__ float nrm[2][64];
    __shared__ float cbuf[2][32];
    __shared__ float sbuf[2][32];
    __shared__ float red2[2][64];
    __shared__ float flg[2];
    const int tid = threadIdx.x;
    const int g = tid >> 6;          // matrix slot within block
    const int r = tid & 63;          // row within matrix
    const int m = blockIdx.x * 2 + g;
    float* gb = g_cbuf + (size_t)m * 4096;
    float* S = smA[g];

    // float4 coalesced load into padded smem
    #pragma unroll
    for (int it = 0; it < 16; ++it) {
        int idx = it * 256 + r * 4;
        float4 v = *(const float4*)(gb + idx);
        float* p = S + (idx >> 6) * 65 + (idx & 63);
        p[0] = v.x; p[1] = v.y; p[2] = v.z; p[3] = v.w;
    }
    __syncthreads();
    {
        float s = 0.0f;
        #pragma unroll
        for (int a = 0; a < 64; ++a) { float v = S[a * 65 + r]; s += v * v; }
        nrm[g][r] = s;
    }
    float w[64];
    #pragma unroll
    for (int j = 0; j < 64; ++j) w[j] = S[r * 65 + j];
    __syncthreads();

    #pragma unroll 1
    for (int sw = 0; sw < MAXSWEEP; ++sw) {
        float gacc = 0.0f;
        #pragma unroll
        for (int rnd = 0; rnd < 63; ++rnd) {
            // products for the 32 position-pairs (literal indices)
            S[0 * 65 + r] = w[0] * w[63];
            #pragma unroll
            for (int k = 1; k < 32; ++k)
                S[k * 65 + r] = w[k] * w[63 - k];
            __syncthreads();
            // split partial reduction: all 64 threads, 32-element halves
            {
                int p = r & 31, h = r >> 5;
                const float* row = S + p * 65 + h * 32;
                float part = 0.0f;
                #pragma unroll
                for (int a = 0; a < 32; ++a) part += row[a];
                red2[g][r] = part;
            }
            __syncthreads();
            // angles: lanes 0..31 of each matrix's first warp
            if (r < 32) {
                float gam = red2[g][r] + red2[g][r + 32];
                const int A = (r == 0) ? 0 : r;
                const int B = (r == 0) ? 63 : 63 - r;
                float al = nrm[g][A], be = nrm[g][B];
                float c = 1.0f, s = 0.0f;
                if (fabsf(gam) > 1e-37f) {
                    float tau = (be - al) / (2.0f * gam);
                    float t = copysignf(1.0f, tau) /
                              (fabsf(tau) + sqrtf(1.0f + tau * tau));
                    c = rsqrtf(1.0f + t * t);
                    s = t * c;
                    float cs = c * s;
                    float nal = c * c * al - 2.0f * cs * gam + s * s * be;
                    float nbe = s * s * al + 2.0f * cs * gam + c * c * be;
                    al = nal; be = nbe;
                }
                __syncwarp();
                const int sA = (r == 0) ? 0 : r + 1;
                const int sB = (r == 0) ? 1 : 64 - r;
                nrm[g][sA] = al;
                nrm[g][sB] = be;
                cbuf[g][r] = c; sbuf[g][r] = s;
                gacc += gam * gam;
            }
            __syncthreads();
            // rotate pairs in registers (literal indices), then shift ring
            {
                float c0 = cbuf[g][0], s0 = sbuf[g][0];
                float vp = w[0], vq = w[63];
                w[0]  = c0 * vp - s0 * vq;
                w[63] = s0 * vp + c0 * vq;
            }
            #pragma unroll
            for (int k = 1; k < 32; ++k) {
                float c = cbuf[g][k], s = sbuf[g][k];
                float vp = w[k], vq = w[63 - k];
                w[k]      = c * vp - s * vq;
                w[63 - k] = s * vp + c * vq;
            }
            {
                float tmp = w[63];
                #pragma unroll
                for (int i = 62; i >= 1; --i) w[i + 1] = w[i];
                w[1] = tmp;
            }
        }
        // convergence per matrix: sum gamma^2 this sweep vs sum lambda^2
        if (r < 32) {
            float tot = gacc;
            float d = nrm[g][r] * nrm[g][r] + nrm[g][r + 32] * nrm[g][r + 32];
            #pragma unroll
            for (int o = 16; o > 0; o >>= 1) {
                tot += __shfl_xor_sync(0xFFFFFFFFu, tot, o);
                d   += __shfl_xor_sync(0xFFFFFFFFu, d, o);
            }
            if (r == 0)
                flg[g] = (tot <= JTOL1S * d + 1e-30f) ? 1.0f : 0.0f;
        }
        __syncthreads();
        bool done = (flg[0] != 0.0f) && (flg[1] != 0.0f);
        __syncthreads();
        if (done) break;
    }

    // store rotated rows; exact eigenvalues; coalesced write-back
    #pragma unroll
    for (int j = 0; j < 64; ++j) S[r * 65 + j] = w[j];
    __syncthreads();
    {
        float s = 0.0f;
        #pragma unroll
        for (int a = 0; a < 64; ++a) { float v = S[a * 65 + r]; s += v * v; }
        g_lam[(size_t)m * 64 + r] = s;
    }
    #pragma unroll
    for (int it = 0; it < 16; ++it) {
        int idx = it * 256 + r * 4;
        const float* p = S + (idx >> 6) * 65 + (idx & 63);
        float4 v; v.x = p[0]; v.y = p[1]; v.z = p[2]; v.w = p[3];
        *(float4*)(gb + idx) = v;
    }
}

// ---------------------------------------------------------------------------
// k_pair_pre: dual chol(G, X0), trsm -> F_c (g_cbuf) and dense L_G (g_glbuf)
// ---------------------------------------------------------------------------
__global__ void __launch_bounds__(256, 4) k_pair_pre(const float* __restrict__ x) {
    extern __shared__ float sm[];
    float* s0 = sm;               // G -> cholG
    float* s1 = sm + SLOT;        // X0 -> cholX -> F_c
    float* fv  = sm + 2 * SLOT;   // 64
    float* vec = fv + 64;         // 64
    const int tid = threadIdx.x;
    const int b  = blockIdx.x;
    const int nb = b >> 3, pp = b & 7;
    const int c0 = (pp & 1) + ((pp >> 1) << 2);
    const float* X0 = x + (size_t)(nb * 16 + c0) * 4096;
    const float* X1 = X0 + 2 * 4096;
    const float w0 = g_w01[0], w1 = g_w01[1];

    for (int i = tid * 4; i < 4096; i += 1024) {
        float4 v0 = *(const float4*)(X0 + i);
        float4 v1 = *(const float4*)(X1 + i);
        float* p0 = s0 + (i >> 6) * LD + (i & 63);
        float* p1 = s1 + (i >> 6) * LD + (i & 63);
        p0[0] = w0 * v0.x + w1 * v1.x;
        p0[1] = w0 * v0.y + w1 * v1.y;
        p0[2] = w0 * v0.z + w1 * v1.z;
        p0[3] = w0 * v0.w + w1 * v1.w;
        p1[0] = v0.x; p1[1] = v0.y; p1[2] = v0.z; p1[3] = v0.w;
    }
    __syncthreads();
    chol_u2(s0, s1);              // both factorizations, shared barriers
    if (tid < 64) fv[tid] = s1[tid * 66];
    __syncthreads();
    for (int i = tid; i < 4096; i += 256) {
        int r = i >> 6, c = i & 63;
        float d = fmaxf(fv[c], 1e-30f);
        float v = (c < r) ? s1[r * LD + c] * rsqrtf(d)
                          : ((c == r) ? sqrtf(d) : 0.0f);
        s1[r * LD + c] = v;                    // Lx (upper zeroed)
    }
    __syncthreads();
    trsm_left(s0, s1);                         // Ltil_G^{-1} Lx (stays lower)
    if (tid < 64) vec[tid] = rsqrtf(fmaxf(s0[tid * 66], 1e-30f));
    __syncthreads();
    for (int i = tid * 4; i < 4096; i += 1024) {
        int r = i >> 6, cb = i & 63;
        const float* p1 = s1 + r * LD + cb;
        float4 fc, lg;
        float rv = vec[r];
        fc.x = p1[0] * rv; fc.y = p1[1] * rv;
        fc.z = p1[2] * rv; fc.w = p1[3] * rv;
        #pragma unroll
        for (int j = 0; j < 4; ++j) {
            int c = cb + j;
            float d = fmaxf(s0[c * 66], 1e-30f);
            float lv = (c < r) ? s0[r * LD + c] * rsqrtf(d)
                               : ((c == r) ? sqrtf(d) : 0.0f);
            ((float*)&lg)[j] = lv;
        }
        *(float4*)(g_cbuf  + (size_t)b * 4096 + i) = fc;
        *(float4*)(g_glbuf + (size_t)b * 4096 + i) = lg;
    }
}

// ---------------------------------------------------------------------------
// k_pair_post: F_b = L_G W diag(sqrt(g/l)); bary = F_b F_b^T
// ---------------------------------------------------------------------------
__global__ void __launch_bounds__(256, 4) k_pair_post() {
    extern __shared__ float sm[];
    float* s0 = sm;               // L_G (lower-tri, upper zero)
    float* s1 = sm + SLOT;        // W -> F_b
    float* fv = sm + 2 * SLOT;    // 64
    const int tid = threadIdx.x;
    const int b = blockIdx.x;
    const float w0 = g_w01[0], w1 = g_w01[1];
    gload(s0, g_glbuf + (size_t)b * 4096);
    gload(s1, g_cbuf + (size_t)b * 4096);
    if (tid < 64) {
        float a = fmaxf(g_lam[(size_t)b * 64 + tid], 1e-12f);
        float bb = fmaxf((1.0f - w0 * a) / w1, 1e-12f);
        float g = expf(w0 * logf(a) + w1 * logf(bb));
        fv[tid] = sqrtf(g / a);
    }
    __syncthreads();
    for (int i = tid; i < 4096; i += 256) {
        int r = i >> 6, c = i & 63;
        s1[r * LD + c] *= fv[c];
    }
    __syncthreads();
    mm_ltA(s1, s0, s1);           // F_b = L_G * W' (triangular A, in-place)
    float* fb = g_fbuf + (size_t)b * 4096;
    for (int i = tid * 4; i < 4096; i += 1024) {
        const float* p = s1 + (i >> 6) * LD + (i & 63);
        float4 v; v.x = p[0]; v.y = p[1]; v.z = p[2]; v.w = p[3];
        *(float4*)(fb + i) = v;
    }
    mm_nt_g(g_abuf + (size_t)b * 4096, s1, s1);
}

// ---------------------------------------------------------------------------
// means: 2-stage deterministic (stage 1 float4)
// ---------------------------------------------------------------------------
__global__ void k_meanA_s1() {
    const int e = (blockIdx.x * 256 + threadIdx.x) * 4;
    const int m0 = blockIdx.y * 512;
    float4 s = make_float4(0.f, 0.f, 0.f, 0.f);
    #pragma unroll 4
    for (int m = 0; m < 512; ++m) {
        float4 v = *(const float4*)(g_abuf + (size_t)(m0 + m) * 4096 + e);
        s.x += v.x; s.y += v.y; s.z += v.z; s.w += v.w;
    }
    *(float4*)(g_part + blockIdx.y * 4096 + e) = s;
}
__global__ void k_meanA_s2() {
    const int e = blockIdx.x * 256 + threadIdx.x;
    float s = 0.0f;
    #pragma unroll
    for (int w = 0; w < 8; ++w) s += g_part[w * 4096 + e];
    g_G0[e] = s * (1.0f / 4096.0f);
}
__global__ void k_meanL_s1() {
    const int e = (blockIdx.x * 256 + threadIdx.x) * 4;
    const int m0 = blockIdx.y * 512;
    float4 s = make_float4(0.f, 0.f, 0.f, 0.f);
    #pragma unroll 4
    for (int m = 0; m < 512; ++m) {
        float4 v = *(const float4*)(g_lbuf + (size_t)(m0 + m) * 4096 + e);
        s.x += v.x; s.y += v.y; s.z += v.z; s.w += v.w;
    }
    *(float4*)(g_part + blockIdx.y * 4096 + e) = s;
}
__global__ void k_meanL_s2() {
    const int e = blockIdx.x * 256 + threadIdx.x;
    float s = 0.0f;
    #pragma unroll
    for (int w = 0; w < 8; ++w) s += g_part[w * 4096 + e];
    g_Sbar[e] = s * (1.0f / 4096.0f);
}

// ---------------------------------------------------------------------------
// K4: Cholesky of G0 -> dense L0 and L0^{-1} (single block)
// ---------------------------------------------------------------------------
__global__ void __launch_bounds__(256, 1) k_g0() {
    extern __shared__ float sm[];
    float* s0 = sm;
    float* s1 = sm + SLOT;
    const int tid = threadIdx.x;
    gload(s0, g_G0);
    chol_u(s0);
    for (int i = tid; i < 4096; i += 256) {
        int r = i >> 6, c = i & 63;
        float d = fmaxf(s0[c * 66], 1e-30f);
        float v = (c < r) ? s0[r * LD + c] * rsqrtf(d)
                          : ((c == r) ? sqrtf(d) : 0.0f);
        g_L0[i] = v;
        s1[r * LD + c] = (r == c) ? 1.0f : 0.0f;
    }
    __syncthreads();
    trsm_left(s0, s1);            // identity is lower-tri; result lower-tri
    for (int i = tid; i < 4096; i += 256) {
        int r = i >> 6, c = i & 63;
        g_Li0[i] = rsqrtf(fmaxf(s0[r * 66], 1e-30f)) * s1[r * LD + c];
    }
}

// ---------------------------------------------------------------------------
// k_bn1_pre: Fm = Li0 F_b -> g_cbuf  (Li0 lower-triangular)
// ---------------------------------------------------------------------------
__global__ void __launch_bounds__(256, 4) k_bn1_pre() {
    extern __shared__ float sm[];
    float* s0 = sm;
    float* s1 = sm + SLOT;
    const int tid = threadIdx.x;
    const int m = blockIdx.x;
    gload(s0, g_Li0);
    gload(s1, g_fbuf + (size_t)m * 4096);
    mm_ltA(s1, s0, s1);           // triangular A, in-place
    for (int i = tid * 4; i < 4096; i += 1024) {
        const float* p = s1 + (i >> 6) * LD + (i & 63);
        float4 v; v.x = p[0]; v.y = p[1]; v.z = p[2]; v.w = p[3];
        *(float4*)(g_cbuf + (size_t)m * 4096 + i) = v;
    }
}

// ---------------------------------------------------------------------------
// k_bn1_post: L_m = W diag(log l / l) W^T -> g_lbuf
// ---------------------------------------------------------------------------
__global__ void __launch_bounds__(256, 4) k_bn1_post() {
    extern __shared__ float sm[];
    float* s1 = sm;
    float* fv = sm + SLOT;
    const int tid = threadIdx.x;
    const int m = blockIdx.x;
    gload(s1, g_cbuf + (size_t)m * 4096);
    if (tid < 64) {
        float l = fmaxf(g_lam[(size_t)m * 64 + tid], 1e-12f);
        fv[tid] = logf(l) / l;
    }
    __syncthreads();
    mm_recon_g(g_lbuf + (size_t)m * 4096, s1, fv);
}

// ---------------------------------------------------------------------------
// K7: bary = L0 expm(Sbar) L0^T; T = bnw^{1/2} @ bary^{-1/2}. single block.
// ---------------------------------------------------------------------------
__global__ void __launch_bounds__(256, 1) k_bary(const float* __restrict__ bnw) {
    extern __shared__ float sm[];
    float* s0 = sm;
    float* s1 = sm + SLOT;
    float* s2 = sm + 2 * SLOT;
    float* s3 = sm + 3 * SLOT;
    float* red = sm + 4 * SLOT;
    float* vec = red + 24;
    const int tid = threadIdx.x;

    gload(s0, g_Sbar);
    sexpm(s0, s1, s2, red);
    gload(s0, g_L0);
    mm_nn(s2, s0, s1);
    mm_nt(s1, s2, s0);               // bary
    float lam = spec_est(s1, vec, red);
    float csc = 1.15f * lam, ic = 1.0f / csc;
    for (int i = tid; i < 4096; i += 256) {
        int r = i >> 6, c = i & 63;
        s1[r * LD + c] *= ic;
        s3[r * LD + c] = (r == c) ? 1.0f : 0.0f;
    }
    __syncthreads();
    ns_sqrt(s1, s3, s2, red);
    float irc = rsqrtf(csc);
    for (int i = tid; i < 4096; i += 256) {
        int r = i >> 6, c = i & 63;
        s3[r * LD + c] *= irc;       // bary^{-1/2}
    }
    __syncthreads();
    gload(s0, bnw);
    float lam2 = spec_est(s0, vec, red);
    float c2 = 1.15f * lam2, ic2 = 1.0f / c2;
    for (int i = tid; i < 4096; i += 256) {
        int r = i >> 6, c = i & 63;
        s0[r * LD + c] *= ic2;
        s1[r * LD + c] = (r == c) ? 1.0f : 0.0f;
    }
    __syncthreads();
    ns_sqrt(s0, s1, s2, red);
    float rc2 = sqrtf(c2);
    for (int i = tid; i < 4096; i += 256) {
        int r = i >> 6, c = i & 63;
        s0[r * LD + c] *= rc2;       // Ws
    }
    __syncthreads();
    mm_nn_g(g_T, s0, s3);            // T
}

// ---------------------------------------------------------------------------
// K8: out = T M T^T
// ---------------------------------------------------------------------------
__global__ void __launch_bounds__(256, 4) k_out(float* __restrict__ out) {
    extern __shared__ float sm[];
    float* MG = sm;
    float* MA = sm + SLOT;
    float* MT = sm + 2 * SLOT;
    const int m = blockIdx.x;
    gload(MG, g_T);
    gload(MA, g_abuf + (size_t)m * 4096);
    mm_nn(MT, MG, MA);
    mm_nt_g(out + (size_t)m * 4096, MT, MG);
}

// ---------------------------------------------------------------------------
extern "C" void kernel_launch(void* const* d_in, const int* in_sizes, int n_in,
                              void* d_out, int out_size) {
    const float* x   = (const float*)d_in[0];
    const float* w1  = (const float*)d_in[1];
    const float* bnw = (const float*)d_in[2];
    float* out = (float*)d_out;

    const int sm4t = (4 * SLOT + TAIL) * (int)sizeof(float);
    const int sm3  = (3 * SLOT) * (int)sizeof(float);
    const int sm2t = (2 * SLOT + TAIL) * (int)sizeof(float);
    const int sm2  = (2 * SLOT) * (int)sizeof(float);

    cudaFuncSetAttribute(k_pair_pre,  cudaFuncAttributeMaxDynamicSharedMemorySize, sm2t);
    cudaFuncSetAttribute(k_pair_post, cudaFuncAttributeMaxDynamicSharedMemorySize, sm2t);
    cudaFuncSetAttribute(k_g0,        cudaFuncAttributeMaxDynamicSharedMemorySize, sm2);
    cudaFuncSetAttribute(k_bn1_pre,   cudaFuncAttributeMaxDynamicSharedMemorySize, sm2);
    cudaFuncSetAttribute(k_bn1_post,  cudaFuncAttributeMaxDynamicSharedMemorySize, sm2t);
    cudaFuncSetAttribute(k_bary,      cudaFuncAttributeMaxDynamicSharedMemorySize, sm4t);
    cudaFuncSetAttribute(k_out,       cudaFuncAttributeMaxDynamicSharedMemorySize, sm3);

    k_softmax<<<1, 1>>>(w1);
    k_pair_pre<<<4096, 256, sm2t>>>(x);
    k_eig<<<2048, 128>>>();
    k_pair_post<<<4096, 256, sm2t>>>();
    k_meanA_s1<<<dim3(4, 8), 256>>>();
    k_meanA_s2<<<16, 256>>>();
    k_g0<<<1, 256, sm2>>>();
    k_bn1_pre<<<4096, 256, sm2>>>();
    k_eig<<<2048, 128>>>();
    k_bn1_post<<<4096, 256, sm2t>>>();
    k_meanL_s1<<<dim3(4, 8), 256>>>();
    k_meanL_s2<<<16, 256>>>();
    k_bary<<<1, 256, sm4t>>>(bnw);
    k_out<<<4096, 256, sm3>>>(out);
    (void)in_sizes; (void)n_in; (void)out_size;
}

// round 16
// speedup vs baseline: 1.0441x; 1.0270x over previous
#include <cuda_runtime.h>
#include <math.h>

// ---------------------------------------------------------------------------
// DiMap SPD pipeline, round 15.
// k_eig rebuilt: 1 matrix per 64-thread block (no convergence coupling),
// products written as 8x STS.128 (stride-36 buffer, conflict-free), c/s as
// float2 broadcasts, split 64-thread reduction with ILP tree.
// All other kernels identical to R14/R13. JTOL1S = 1e-5 (safe accuracy).
// ---------------------------------------------------------------------------

#define LD 65
#define SLOT (64 * LD)
#define TAIL 384
#define MAXSWEEP 10
#define JTOL1S 1e-5f
#define NSMAX 13
#define PST 36   // product-buffer row stride (floats); PST/4 odd -> .128 ok

// --- scratch ---------------------------------------------------------------
__device__ float g_abuf[16777216];   // bary matrices
__device__ float g_fbuf[16777216];   // bary factors
__device__ float g_lbuf[16777216];   // log matrices
__device__ float g_cbuf[16777216];   // eig factor (in/out of k_eig)
__device__ float g_glbuf[16777216];  // per-pair dense L_G
__device__ float g_lam[262144];      // 4096 x 64 eigenvalues
__device__ float g_part[32768];
__device__ float g_w01[2];
__device__ float g_G0[4096];
__device__ float g_Sbar[4096];
__device__ float g_L0[4096];
__device__ float g_Li0[4096];
__device__ float g_T[4096];

// ---------------------------------------------------------------------------
__device__ float block_sum(float v, float* red) {
    const int tid = threadIdx.x;
    #pragma unroll
    for (int o = 16; o > 0; o >>= 1) v += __shfl_xor_sync(0xFFFFFFFFu, v, o);
    __syncthreads();
    if ((tid & 31) == 0) red[tid >> 5] = v;
    __syncthreads();
    if (tid == 0) {
        float s = 0.0f;
        #pragma unroll
        for (int w = 0; w < 8; ++w) s += red[w];
        red[8] = s;
    }
    __syncthreads();
    float r = red[8];
    __syncthreads();
    return r;
}

__device__ float spec_est(const float* A, float* vec, float* red) {
    const int tid = threadIdx.x;
    if (tid < 64) vec[tid] = 1.0f;
    __syncthreads();
    float m = 1.0f;
    for (int it = 0; it < 6; ++it) {
        float y = 0.0f;
        if (tid < 64) {
            #pragma unroll 8
            for (int k = 0; k < 64; ++k) y += A[tid * LD + k] * vec[k];
            float a = fabsf(y);
            #pragma unroll
            for (int o = 16; o > 0; o >>= 1)
                a = fmaxf(a, __shfl_xor_sync(0xFFFFFFFFu, a, o));
            if ((tid & 31) == 0) red[tid >> 5] = a;
        }
        __syncthreads();
        m = fmaxf(red[0], red[1]);
        if (tid < 64) vec[tid] = y / m;
        __syncthreads();
    }
    return m;
}

// ---------------------------------------------------------------------------
// Unscaled LDL^T Cholesky, lower triangle only, row-skipped.
// ---------------------------------------------------------------------------
__device__ void chol_u(float* W) {
    const int tid = threadIdx.x;
    for (int j = 0; j < 64; ++j) {
        float dinv = 1.0f / W[j * LD + j];
        for (int it = j >> 2; it < 16; ++it) {
            int i = tid + it * 256;
            int r = i >> 6, c = i & 63;
            if (r > j && c > j && c <= r)
                W[r * LD + c] -= W[r * LD + j] * W[c * LD + j] * dinv;
        }
        __syncthreads();
    }
}

// dual-matrix fused variant: same barriers, both matrices per step
__device__ void chol_u2(float* W0, float* W1) {
    const int tid = threadIdx.x;
    for (int j = 0; j < 64; ++j) {
        float d0 = 1.0f / W0[j * LD + j];
        float d1 = 1.0f / W1[j * LD + j];
        for (int it = j >> 2; it < 16; ++it) {
            int i = tid + it * 256;
            int r = i >> 6, c = i & 63;
            if (r > j && c > j && c <= r) {
                W0[r * LD + c] -= W0[r * LD + j] * W0[c * LD + j] * d0;
                W1[r * LD + c] -= W1[r * LD + j] * W1[c * LD + j] * d1;
            }
        }
        __syncthreads();
    }
}

// X <- Ltil^{-1} X for LOWER-TRIANGULAR X (upper exactly zero and stays so).
__device__ void trsm_left(const float* W, float* X) {
    const int tid = threadIdx.x;
    for (int i = 0; i < 64; ++i) {
        float dinv = 1.0f / W[i * LD + i];
        for (int it = i >> 2; it < 16; ++it) {
            int idx = tid + it * 256;
            int r = idx >> 6, c = idx & 63;
            if (r > i && c <= i)
                X[r * LD + c] -= (W[r * LD + i] * dinv) * X[i * LD + c];
        }
        __syncthreads();
    }
}

// ---------------------------------------------------------------------------
// 64x64 matmuls (256 threads, 4x4 tiles). In-place C==A or C==B is safe.
// ---------------------------------------------------------------------------
__device__ void mm_nn(float* C, const float* A, const float* B) {
    const int t = threadIdx.x;
    const int i0 = (t >> 4) << 2, j0 = (t & 15) << 2;
    float acc[4][4];
    #pragma unroll
    for (int r = 0; r < 4; ++r)
        #pragma unroll
        for (int c = 0; c < 4; ++c) acc[r][c] = 0.0f;
    #pragma unroll 4
    for (int k = 0; k < 64; ++k) {
        float a[4], b[4];
        #pragma unroll
        for (int r = 0; r < 4; ++r) a[r] = A[(i0 + r) * LD + k];
        #pragma unroll
        for (int c = 0; c < 4; ++c) b[c] = B[k * LD + j0 + c];
        #pragma unroll
        for (int r = 0; r < 4; ++r)
            #pragma unroll
            for (int c = 0; c < 4; ++c) acc[r][c] += a[r] * b[c];
    }
    __syncthreads();
    #pragma unroll
    for (int r = 0; r < 4; ++r)
        #pragma unroll
        for (int c = 0; c < 4; ++c) C[(i0 + r) * LD + j0 + c] = acc[r][c];
    __syncthreads();
}

// C = A * B with A LOWER-TRIANGULAR (upper entries exactly zero).
__device__ void mm_ltA(float* C, const float* A, const float* B) {
    const int t = threadIdx.x;
    const int i0 = (t >> 4) << 2, j0 = (t & 15) << 2;
    const int kmax = i0 + 4;
    float acc[4][4];
    #pragma unroll
    for (int r = 0; r < 4; ++r)
        #pragma unroll
        for (int c = 0; c < 4; ++c) acc[r][c] = 0.0f;
    #pragma unroll 4
    for (int k = 0; k < kmax; ++k) {
        float a[4], b[4];
        #pragma unroll
        for (int r = 0; r < 4; ++r) a[r] = A[(i0 + r) * LD + k];
        #pragma unroll
        for (int c = 0; c < 4; ++c) b[c] = B[k * LD + j0 + c];
        #pragma unroll
        for (int r = 0; r < 4; ++r)
            #pragma unroll
            for (int c = 0; c < 4; ++c) acc[r][c] += a[r] * b[c];
    }
    __syncthreads();
    #pragma unroll
    for (int r = 0; r < 4; ++r)
        #pragma unroll
        for (int c = 0; c < 4; ++c) C[(i0 + r) * LD + j0 + c] = acc[r][c];
    __syncthreads();
}

__device__ void mm_nt(float* C, const float* A, const float* B) {
    const int t = threadIdx.x;
    const int i0 = (t >> 4) << 2, j0 = (t & 15) << 2;
    float acc[4][4];
    #pragma unroll
    for (int r = 0; r < 4; ++r)
        #pragma unroll
        for (int c = 0; c < 4; ++c) acc[r][c] = 0.0f;
    #pragma unroll 4
    for (int k = 0; k < 64; ++k) {
        float a[4], b[4];
        #pragma unroll
        for (int r = 0; r < 4; ++r) a[r] = A[(i0 + r) * LD + k];
        #pragma unroll
        for (int c = 0; c < 4; ++c) b[c] = B[(j0 + c) * LD + k];
        #pragma unroll
        for (int r = 0; r < 4; ++r)
            #pragma unroll
            for (int c = 0; c < 4; ++c) acc[r][c] += a[r] * b[c];
    }
    __syncthreads();
    #pragma unroll
    for (int r = 0; r < 4; ++r)
        #pragma unroll
        for (int c = 0; c < 4; ++c) C[(i0 + r) * LD + j0 + c] = acc[r][c];
    __syncthreads();
}

__device__ void mm_nn_g(float* Cg, const float* A, const float* B) {
    const int t = threadIdx.x;
    const int i0 = (t >> 4) << 2, j0 = (t & 15) << 2;
    float acc[4][4];
    #pragma unroll
    for (int r = 0; r < 4; ++r)
        #pragma unroll
        for (int c = 0; c < 4; ++c) acc[r][c] = 0.0f;
    #pragma unroll 4
    for (int k = 0; k < 64; ++k) {
        float a[4], b[4];
        #pragma unroll
        for (int r = 0; r < 4; ++r) a[r] = A[(i0 + r) * LD + k];
        #pragma unroll
        for (int c = 0; c < 4; ++c) b[c] = B[k * LD + j0 + c];
        #pragma unroll
        for (int r = 0; r < 4; ++r)
            #pragma unroll
            for (int c = 0; c < 4; ++c) acc[r][c] += a[r] * b[c];
    }
    #pragma unroll
    for (int r = 0; r < 4; ++r)
        #pragma unroll
        for (int c = 0; c < 4; ++c) Cg[(i0 + r) * 64 + j0 + c] = acc[r][c];
    __syncthreads();
}

__device__ void mm_nt_g(float* Cg, const float* A, const float* B) {
    const int t = threadIdx.x;
    const int i0 = (t >> 4) << 2, j0 = (t & 15) << 2;
    float acc[4][4];
    #pragma unroll
    for (int r = 0; r < 4; ++r)
        #pragma unroll
        for (int c = 0; c < 4; ++c) acc[r][c] = 0.0f;
    #pragma unroll 4
    for (int k = 0; k < 64; ++k) {
        float a[4], b[4];
        #pragma unroll
        for (int r = 0; r < 4; ++r) a[r] = A[(i0 + r) * LD + k];
        #pragma unroll
        for (int c = 0; c < 4; ++c) b[c] = B[(j0 + c) * LD + k];
        #pragma unroll
        for (int r = 0; r < 4; ++r)
            #pragma unroll
            for (int c = 0; c < 4; ++c) acc[r][c] += a[r] * b[c];
    }
    #pragma unroll
    for (int r = 0; r < 4; ++r)
        #pragma unroll
        for (int c = 0; c < 4; ++c) Cg[(i0 + r) * 64 + j0 + c] = acc[r][c];
    __syncthreads();
}

// Cg(gmem) = V diag(f) V^T
__device__ void mm_recon_g(float* Cg, const float* V, const float* f) {
    const int t = threadIdx.x;
    const int i0 = (t >> 4) << 2, j0 = (t & 15) << 2;
    float acc[4][4];
    #pragma unroll
    for (int r = 0; r < 4; ++r)
        #pragma unroll
        for (int c = 0; c < 4; ++c) acc[r][c] = 0.0f;
    #pragma unroll 4
    for (int k = 0; k < 64; ++k) {
        float fk = f[k];
        float a[4], b[4];
        #pragma unroll
        for (int r = 0; r < 4; ++r) a[r] = V[(i0 + r) * LD + k] * fk;
        #pragma unroll
        for (int c = 0; c < 4; ++c) b[c] = V[(j0 + c) * LD + k];
        #pragma unroll
        for (int r = 0; r < 4; ++r)
            #pragma unroll
            for (int c = 0; c < 4; ++c) acc[r][c] += a[r] * b[c];
    }
    #pragma unroll
    for (int r = 0; r < 4; ++r)
        #pragma unroll
        for (int c = 0; c < 4; ++c) Cg[(i0 + r) * 64 + j0 + c] = acc[r][c];
    __syncthreads();
}

// float4 gmem -> padded smem
__device__ void gload(float* M, const float* g) {
    for (int i = threadIdx.x * 4; i < 4096; i += 1024) {
        float4 v = *(const float4*)(g + i);
        float* p = M + (i >> 6) * LD + (i & 63);
        p[0] = v.x; p[1] = v.y; p[2] = v.z; p[3] = v.w;
    }
    __syncthreads();
}

// ---------------------------------------------------------------------------
// NS + sexpm (k_bary only)
// ---------------------------------------------------------------------------
__device__ void ns_sqrt(float* Y, float* Z, float* T, float* red) {
    const int tid = threadIdx.x;
    for (int it = 0; it < NSMAX; ++it) {
        mm_nn(T, Z, Y);
        float mx = 0.0f;
        for (int i = tid; i < 4096; i += 256) {
            int r = i >> 6, c = i & 63;
            float v = T[r * LD + c];
            float t = ((r == c) ? 1.5f : 0.0f) - 0.5f * v;
            T[r * LD + c] = t;
            mx = fmaxf(mx, fabsf(t - ((r == c) ? 1.0f : 0.0f)));
        }
        __syncthreads();
        #pragma unroll
        for (int o = 16; o > 0; o >>= 1)
            mx = fmaxf(mx, __shfl_xor_sync(0xFFFFFFFFu, mx, o));
        if ((tid & 31) == 0) red[tid >> 5] = mx;
        __syncthreads();
        if (tid == 0) {
            float g = 0.0f;
            #pragma unroll
            for (int w = 0; w < 8; ++w) g = fmaxf(g, red[w]);
            red[8] = g;
        }
        __syncthreads();
        float g = red[8];
        __syncthreads();
        if (g < 3e-8f) break;
        mm_nn(Y, Y, T);
        mm_nn(Z, T, Z);
    }
}

__device__ void sexpm(float* B, float* Q, float* T, float* red) {
    const int tid = threadIdx.x;
    float s2 = 0.0f;
    for (int i = tid; i < 4096; i += 256) {
        float v = B[(i >> 6) * LD + (i & 63)];
        s2 += v * v;
    }
    float fn = sqrtf(block_sum(s2, red));
    int s = 0; float f = fn;
    while (f > 0.5f && s < 40) { f *= 0.5f; ++s; }
    float scale = ldexpf(1.0f, -s);
    for (int i = tid; i < 4096; i += 256)
        B[(i >> 6) * LD + (i & 63)] *= scale;
    __syncthreads();
    for (int i = tid; i < 4096; i += 256) {
        int r = i >> 6, c = i & 63;
        Q[r * LD + c] = ((r == c) ? 1.0f : 0.0f) + 0.1f * B[r * LD + c];
    }
    __syncthreads();
    for (int k = 9; k >= 1; --k) {
        mm_nn(T, B, Q);
        float inv = 1.0f / (float)k;
        for (int i = tid; i < 4096; i += 256) {
            int r = i >> 6, c = i & 63;
            Q[r * LD + c] = ((r == c) ? 1.0f : 0.0f) + inv * T[r * LD + c];
        }
        __syncthreads();
    }
    for (int i = 0; i < s; ++i) mm_nn(Q, Q, Q);
}

// ---------------------------------------------------------------------------
__global__ void k_softmax(const float* __restrict__ wv) {
    float a = wv[0], b = wv[1];
    float m = fmaxf(a, b);
    float ea = expf(a - m), eb = expf(b - m);
    float inv = 1.0f / (ea + eb);
    g_w01[0] = ea * inv;
    g_w01[1] = eb * inv;
}

// ---------------------------------------------------------------------------
// k_eig: register-resident one-sided Jacobi, circle-method positions.
// 64 threads, ONE matrix. Products via 8x STS.128 (stride-36, conflict-free
// per quarter-warp), split 64-thread reduction, float2 c/s broadcasts.
// ---------------------------------------------------------------------------
__global__ void __launch_bounds__(64) k_eig() {
    __shared__ float sm[64 * 65];      // staging for load/store
    __shared__ float P[64 * PST];      // products, row-major, stride 36
    __shared__ float nrm[64];
    __shared__ float2 cs[32];
    __shared__ float red2[64];
    __shared__ float flag;
    const int r = threadIdx.x;
    const int m = blockIdx.x;
    float* gb = g_cbuf + (size_t)m * 4096;

    // float4 coalesced load into padded smem
    #pragma unroll
    for (int it = 0; it < 16; ++it) {
        int idx = it * 256 + r * 4;
        float4 v = *(const float4*)(gb + idx);
        float* p = sm + (idx >> 6) * 65 + (idx & 63);
        p[0] = v.x; p[1] = v.y; p[2] = v.z; p[3] = v.w;
    }
    __syncthreads();
    {
        float s = 0.0f;
        #pragma unroll
        for (int a = 0; a < 64; ++a) { float v = sm[a * 65 + r]; s += v * v; }
        nrm[r] = s;
    }
    float w[64];
    #pragma unroll
    for (int j = 0; j < 64; ++j) w[j] = sm[r * 65 + j];
    __syncthreads();

    #pragma unroll 1
    for (int sw = 0; sw < MAXSWEEP; ++sw) {
        float gacc = 0.0f;
        #pragma unroll
        for (int rnd = 0; rnd < 63; ++rnd) {
            // products for 32 position-pairs -> P[r][0..31], 8x STS.128
            {
                float pr[32];
                pr[0] = w[0] * w[63];
                #pragma unroll
                for (int k = 1; k < 32; ++k) pr[k] = w[k] * w[63 - k];
                float4* Pr = (float4*)(P + r * PST);
                #pragma unroll
                for (int q = 0; q < 8; ++q)
                    Pr[q] = make_float4(pr[4 * q], pr[4 * q + 1],
                                        pr[4 * q + 2], pr[4 * q + 3]);
            }
            __syncthreads();
            // split reduction: thread t sums 32 rows of column (t&31)
            {
                int p = r & 31, h = r >> 5;
                const float* col = P + (h * 32) * PST + p;
                float s0 = 0.0f, s1 = 0.0f, s2 = 0.0f, s3 = 0.0f;
                #pragma unroll
                for (int a = 0; a < 32; a += 4) {
                    s0 += col[(a + 0) * PST];
                    s1 += col[(a + 1) * PST];
                    s2 += col[(a + 2) * PST];
                    s3 += col[(a + 3) * PST];
                }
                red2[r] = (s0 + s1) + (s2 + s3);
            }
            __syncthreads();
            // angles: lanes 0..31
            if (r < 32) {
                float gam = red2[r] + red2[r + 32];
                const int A = (r == 0) ? 0 : r;
                const int B = (r == 0) ? 63 : 63 - r;
                float al = nrm[A], be = nrm[B];
                float c = 1.0f, s = 0.0f;
                if (fabsf(gam) > 1e-37f) {
                    float tau = (be - al) / (2.0f * gam);
                    float t = copysignf(1.0f, tau) /
                              (fabsf(tau) + sqrtf(1.0f + tau * tau));
                    c = rsqrtf(1.0f + t * t);
                    s = t * c;
                    float csv = c * s;
                    float nal = c * c * al - 2.0f * csv * gam + s * s * be;
                    float nbe = s * s * al + 2.0f * csv * gam + c * c * be;
                    al = nal; be = nbe;
                }
                __syncwarp();
                // write norms to post-shift positions
                const int sA = (r == 0) ? 0 : r + 1;
                const int sB = (r == 0) ? 1 : 64 - r;
                nrm[sA] = al;
                nrm[sB] = be;
                cs[r] = make_float2(c, s);
                gacc += gam * gam;
            }
            __syncthreads();
            // rotate pairs (float2 broadcasts), then shift ring
            {
                float2 q0 = cs[0];
                float vp = w[0], vq = w[63];
                w[0]  = q0.x * vp - q0.y * vq;
                w[63] = q0.y * vp + q0.x * vq;
            }
            #pragma unroll
            for (int k = 1; k < 32; ++k) {
                float2 q = cs[k];
                float vp = w[k], vq = w[63 - k];
                w[k]      = q.x * vp - q.y * vq;
                w[63 - k] = q.y * vp + q.x * vq;
            }
            {
                float tmp = w[63];
                #pragma unroll
                for (int i = 62; i >= 1; --i) w[i + 1] = w[i];
                w[1] = tmp;
            }
        }
        // convergence: sum gamma^2 this sweep vs sum lambda^2
        if (r < 32) {
            float tot = gacc;
            float d = nrm[r] * nrm[r] + nrm[r + 32] * nrm[r + 32];
            #pragma unroll
            for (int o = 16; o > 0; o >>= 1) {
                tot += __shfl_xor_sync(0xFFFFFFFFu, tot, o);
                d   += __shfl_xor_sync(0xFFFFFFFFu, d, o);
            }
            if (r == 0) flag = (tot <= JTOL1S * d + 1e-30f) ? 1.0f : 0.0f;
        }
        __syncthreads();
        if (flag != 0.0f) break;
    }

    // store rotated rows; exact eigenvalues; coalesced write-back
    #pragma unroll
    for (int j = 0; j < 64; ++j) sm[r * 65 + j] = w[j];
    __syncthreads();
    {
        float s = 0.0f;
        #pragma unroll
        for (int a = 0; a < 64; ++a) { float v = sm[a * 65 + r]; s += v * v; }
        g_lam[(size_t)m * 64 + r] = s;
    }
    #pragma unroll
    for (int it = 0; it < 16; ++it) {
        int idx = it * 256 + r * 4;
        const float* p = sm + (idx >> 6) * 65 + (idx & 63);
        float4 v; v.x = p[0]; v.y = p[1]; v.z = p[2]; v.w = p[3];
        *(float4*)(gb + idx) = v;
    }
}

// ---------------------------------------------------------------------------
// k_pair_pre: dual chol(G, X0), trsm -> F_c (g_cbuf) and dense L_G (g_glbuf)
// ---------------------------------------------------------------------------
__global__ void __launch_bounds__(256, 4) k_pair_pre(const float* __restrict__ x) {
    extern __shared__ float sm[];
    float* s0 = sm;               // G -> cholG
    float* s1 = sm + SLOT;        // X0 -> cholX -> F_c
    float* fv  = sm + 2 * SLOT;   // 64
    float* vec = fv + 64;         // 64
    const int tid = threadIdx.x;
    const int b  = blockIdx.x;
    const int nb = b >> 3, pp = b & 7;
    const int c0 = (pp & 1) + ((pp >> 1) << 2);
    const float* X0 = x + (size_t)(nb * 16 + c0) * 4096;
    const float* X1 = X0 + 2 * 4096;
    const float w0 = g_w01[0], w1 = g_w01[1];

    for (int i = tid * 4; i < 4096; i += 1024) {
        float4 v0 = *(const float4*)(X0 + i);
        float4 v1 = *(const float4*)(X1 + i);
        float* p0 = s0 + (i >> 6) * LD + (i & 63);
        float* p1 = s1 + (i >> 6) * LD + (i & 63);
        p0[0] = w0 * v0.x + w1 * v1.x;
        p0[1] = w0 * v0.y + w1 * v1.y;
        p0[2] = w0 * v0.z + w1 * v1.z;
        p0[3] = w0 * v0.w + w1 * v1.w;
        p1[0] = v0.x; p1[1] = v0.y; p1[2] = v0.z; p1[3] = v0.w;
    }
    __syncthreads();
    chol_u2(s0, s1);              // both factorizations, shared barriers
    if (tid < 64) fv[tid] = s1[tid * 66];
    __syncthreads();
    for (int i = tid; i < 4096; i += 256) {
        int r = i >> 6, c = i & 63;
        float d = fmaxf(fv[c], 1e-30f);
        float v = (c < r) ? s1[r * LD + c] * rsqrtf(d)
                          : ((c == r) ? sqrtf(d) : 0.0f);
        s1[r * LD + c] = v;                    // Lx (upper zeroed)
    }
    __syncthreads();
    trsm_left(s0, s1);                         // Ltil_G^{-1} Lx (stays lower)
    if (tid < 64) vec[tid] = rsqrtf(fmaxf(s0[tid * 66], 1e-30f));
    __syncthreads();
    for (int i = tid * 4; i < 4096; i += 1024) {
        int r = i >> 6, cb = i & 63;
        const float* p1 = s1 + r * LD + cb;
        float4 fc, lg;
        float rv = vec[r];
        fc.x = p1[0] * rv; fc.y = p1[1] * rv;
        fc.z = p1[2] * rv; fc.w = p1[3] * rv;
        #pragma unroll
        for (int j = 0; j < 4; ++j) {
            int c = cb + j;
            float d = fmaxf(s0[c * 66], 1e-30f);
            float lv = (c < r) ? s0[r * LD + c] * rsqrtf(d)
                               : ((c == r) ? sqrtf(d) : 0.0f);
            ((float*)&lg)[j] = lv;
        }
        *(float4*)(g_cbuf  + (size_t)b * 4096 + i) = fc;
        *(float4*)(g_glbuf + (size_t)b * 4096 + i) = lg;
    }
}

// ---------------------------------------------------------------------------
// k_pair_post: F_b = L_G W diag(sqrt(g/l)); bary = F_b F_b^T
// ---------------------------------------------------------------------------
__global__ void __launch_bounds__(256, 4) k_pair_post() {
    extern __shared__ float sm[];
    float* s0 = sm;               // L_G (lower-tri, upper zero)
    float* s1 = sm + SLOT;        // W -> F_b
    float* fv = sm + 2 * SLOT;    // 64
    const int tid = threadIdx.x;
    const int b = blockIdx.x;
    const float w0 = g_w01[0], w1 = g_w01[1];
    gload(s0, g_glbuf + (size_t)b * 4096);
    gload(s1, g_cbuf + (size_t)b * 4096);
    if (tid < 64) {
        float a = fmaxf(g_lam[(size_t)b * 64 + tid], 1e-12f);
        float bb = fmaxf((1.0f - w0 * a) / w1, 1e-12f);
        float g = expf(w0 * logf(a) + w1 * logf(bb));
        fv[tid] = sqrtf(g / a);
    }
    __syncthreads();
    for (int i = tid; i < 4096; i += 256) {
        int r = i >> 6, c = i & 63;
        s1[r * LD + c] *= fv[c];
    }
    __syncthreads();
    mm_ltA(s1, s0, s1);           // F_b = L_G * W' (triangular A, in-place)
    float* fb = g_fbuf + (size_t)b * 4096;
    for (int i = tid * 4; i < 4096; i += 1024) {
        const float* p = s1 + (i >> 6) * LD + (i & 63);
        float4 v; v.x = p[0]; v.y = p[1]; v.z = p[2]; v.w = p[3];
        *(float4*)(fb + i) = v;
    }
    mm_nt_g(g_abuf + (size_t)b * 4096, s1, s1);
}

// ---------------------------------------------------------------------------
// means: 2-stage deterministic (stage 1 float4)
// ---------------------------------------------------------------------------
__global__ void k_meanA_s1() {
    const int e = (blockIdx.x * 256 + threadIdx.x) * 4;
    const int m0 = blockIdx.y * 512;
    float4 s = make_float4(0.f, 0.f, 0.f, 0.f);
    #pragma unroll 4
    for (int m = 0; m < 512; ++m) {
        float4 v = *(const float4*)(g_abuf + (size_t)(m0 + m) * 4096 + e);
        s.x += v.x; s.y += v.y; s.z += v.z; s.w += v.w;
    }
    *(float4*)(g_part + blockIdx.y * 4096 + e) = s;
}
__global__ void k_meanA_s2() {
    const int e = blockIdx.x * 256 + threadIdx.x;
    float s = 0.0f;
    #pragma unroll
    for (int w = 0; w < 8; ++w) s += g_part[w * 4096 + e];
    g_G0[e] = s * (1.0f / 4096.0f);
}
__global__ void k_meanL_s1() {
    const int e = (blockIdx.x * 256 + threadIdx.x) * 4;
    const int m0 = blockIdx.y * 512;
    float4 s = make_float4(0.f, 0.f, 0.f, 0.f);
    #pragma unroll 4
    for (int m = 0; m < 512; ++m) {
        float4 v = *(const float4*)(g_lbuf + (size_t)(m0 + m) * 4096 + e);
        s.x += v.x; s.y += v.y; s.z += v.z; s.w += v.w;
    }
    *(float4*)(g_part + blockIdx.y * 4096 + e) = s;
}
__global__ void k_meanL_s2() {
    const int e = blockIdx.x * 256 + threadIdx.x;
    float s = 0.0f;
    #pragma unroll
    for (int w = 0; w < 8; ++w) s += g_part[w * 4096 + e];
    g_Sbar[e] = s * (1.0f / 4096.0f);
}

// ---------------------------------------------------------------------------
// K4: Cholesky of G0 -> dense L0 and L0^{-1} (single block)
// ---------------------------------------------------------------------------
__global__ void __launch_bounds__(256, 1) k_g0() {
    extern __shared__ float sm[];
    float* s0 = sm;
    float* s1 = sm + SLOT;
    const int tid = threadIdx.x;
    gload(s0, g_G0);
    chol_u(s0);
    for (int i = tid; i < 4096; i += 256) {
        int r = i >> 6, c = i & 63;
        float d = fmaxf(s0[c * 66], 1e-30f);
        float v = (c < r) ? s0[r * LD + c] * rsqrtf(d)
                          : ((c == r) ? sqrtf(d) : 0.0f);
        g_L0[i] = v;
        s1[r * LD + c] = (r == c) ? 1.0f : 0.0f;
    }
    __syncthreads();
    trsm_left(s0, s1);            // identity is lower-tri; result lower-tri
    for (int i = tid; i < 4096; i += 256) {
        int r = i >> 6, c = i & 63;
        g_Li0[i] = rsqrtf(fmaxf(s0[r * 66], 1e-30f)) * s1[r * LD + c];
    }
}

// ---------------------------------------------------------------------------
// k_bn1_pre: Fm = Li0 F_b -> g_cbuf  (Li0 lower-triangular)
// ---------------------------------------------------------------------------
__global__ void __launch_bounds__(256, 4) k_bn1_pre() {
    extern __shared__ float sm[];
    float* s0 = sm;
    float* s1 = sm + SLOT;
    const int tid = threadIdx.x;
    const int m = blockIdx.x;
    gload(s0, g_Li0);
    gload(s1, g_fbuf + (size_t)m * 4096);
    mm_ltA(s1, s0, s1);           // triangular A, in-place
    for (int i = tid * 4; i < 4096; i += 1024) {
        const float* p = s1 + (i >> 6) * LD + (i & 63);
        float4 v; v.x = p[0]; v.y = p[1]; v.z = p[2]; v.w = p[3];
        *(float4*)(g_cbuf + (size_t)m * 4096 + i) = v;
    }
}

// ---------------------------------------------------------------------------
// k_bn1_post: L_m = W diag(log l / l) W^T -> g_lbuf
// ---------------------------------------------------------------------------
__global__ void __launch_bounds__(256, 4) k_bn1_post() {
    extern __shared__ float sm[];
    float* s1 = sm;
    float* fv = sm + SLOT;
    const int tid = threadIdx.x;
    const int m = blockIdx.x;
    gload(s1, g_cbuf + (size_t)m * 4096);
    if (tid < 64) {
        float l = fmaxf(g_lam[(size_t)m * 64 + tid], 1e-12f);
        fv[tid] = logf(l) / l;
    }
    __syncthreads();
    mm_recon_g(g_lbuf + (size_t)m * 4096, s1, fv);
}

// ---------------------------------------------------------------------------
// K7: bary = L0 expm(Sbar) L0^T; T = bnw^{1/2} @ bary^{-1/2}. single block.
// ---------------------------------------------------------------------------
__global__ void __launch_bounds__(256, 1) k_bary(const float* __restrict__ bnw) {
    extern __shared__ float sm[];
    float* s0 = sm;
    float* s1 = sm + SLOT;
    float* s2 = sm + 2 * SLOT;
    float* s3 = sm + 3 * SLOT;
    float* red = sm + 4 * SLOT;
    float* vec = red + 24;
    const int tid = threadIdx.x;

    gload(s0, g_Sbar);
    sexpm(s0, s1, s2, red);
    gload(s0, g_L0);
    mm_nn(s2, s0, s1);
    mm_nt(s1, s2, s0);               // bary
    float lam = spec_est(s1, vec, red);
    float csc = 1.15f * lam, ic = 1.0f / csc;
    for (int i = tid; i < 4096; i += 256) {
        int r = i >> 6, c = i & 63;
        s1[r * LD + c] *= ic;
        s3[r * LD + c] = (r == c) ? 1.0f : 0.0f;
    }
    __syncthreads();
    ns_sqrt(s1, s3, s2, red);
    float irc = rsqrtf(csc);
    for (int i = tid; i < 4096; i += 256) {
        int r = i >> 6, c = i & 63;
        s3[r * LD + c] *= irc;       // bary^{-1/2}
    }
    __syncthreads();
    gload(s0, bnw);
    float lam2 = spec_est(s0, vec, red);
    float c2 = 1.15f * lam2, ic2 = 1.0f / c2;
    for (int i = tid; i < 4096; i += 256) {
        int r = i >> 6, c = i & 63;
        s0[r * LD + c] *= ic2;
        s1[r * LD + c] = (r == c) ? 1.0f : 0.0f;
    }
    __syncthreads();
    ns_sqrt(s0, s1, s2, red);
    float rc2 = sqrtf(c2);
    for (int i = tid; i < 4096; i += 256) {
        int r = i >> 6, c = i & 63;
        s0[r * LD + c] *= rc2;       // Ws
    }
    __syncthreads();
    mm_nn_g(g_T, s0, s3);            // T
}

// ---------------------------------------------------------------------------
// K8: out = T M T^T
// ---------------------------------------------------------------------------
__global__ void __launch_bounds__(256, 4) k_out(float* __restrict__ out) {
    extern __shared__ float sm[];
    float* MG = sm;
    float* MA = sm + SLOT;
    float* MT = sm + 2 * SLOT;
    const int m = blockIdx.x;
    gload(MG, g_T);
    gload(MA, g_abuf + (size_t)m * 4096);
    mm_nn(MT, MG, MA);
    mm_nt_g(out + (size_t)m * 4096, MT, MG);
}

// ---------------------------------------------------------------------------
extern "C" void kernel_launch(void* const* d_in, const int* in_sizes, int n_in,
                              void* d_out, int out_size) {
    const float* x   = (const float*)d_in[0];
    const float* w1  = (const float*)d_in[1];
    const float* bnw = (const float*)d_in[2];
    float* out = (float*)d_out;

    const int sm4t = (4 * SLOT + TAIL) * (int)sizeof(float);
    const int sm3  = (3 * SLOT) * (int)sizeof(float);
    const int sm2t = (2 * SLOT + TAIL) * (int)sizeof(float);
    const int sm2  = (2 * SLOT) * (int)sizeof(float);

    cudaFuncSetAttribute(k_pair_pre,  cudaFuncAttributeMaxDynamicSharedMemorySize, sm2t);
    cudaFuncSetAttribute(k_pair_post, cudaFuncAttributeMaxDynamicSharedMemorySize, sm2t);
    cudaFuncSetAttribute(k_g0,        cudaFuncAttributeMaxDynamicSharedMemorySize, sm2);
    cudaFuncSetAttribute(k_bn1_pre,   cudaFuncAttributeMaxDynamicSharedMemorySize, sm2);
    cudaFuncSetAttribute(k_bn1_post,  cudaFuncAttributeMaxDynamicSharedMemorySize, sm2t);
    cudaFuncSetAttribute(k_bary,      cudaFuncAttributeMaxDynamicSharedMemorySize, sm4t);
    cudaFuncSetAttribute(k_out,       cudaFuncAttributeMaxDynamicSharedMemorySize, sm3);

    k_softmax<<<1, 1>>>(w1);
    k_pair_pre<<<4096, 256, sm2t>>>(x);
    k_eig<<<4096, 64>>>();
    k_pair_post<<<4096, 256, sm2t>>>();
    k_meanA_s1<<<dim3(4, 8), 256>>>();
    k_meanA_s2<<<16, 256>>>();
    k_g0<<<1, 256, sm2>>>();
    k_bn1_pre<<<4096, 256, sm2>>>();
    k_eig<<<4096, 64>>>();
    k_bn1_post<<<4096, 256, sm2t>>>();
    k_meanL_s1<<<dim3(4, 8), 256>>>();
    k_meanL_s2<<<16, 256>>>();
    k_bary<<<1, 256, sm4t>>>(bnw);
    k_out<<<4096, 256, sm3>>>(out);
    (void)in_sizes; (void)n_in; (void)out_size;
}